// round 14
// baseline (speedup 1.0000x reference)
#include <cuda_runtime.h>
#include <cuda_bf16.h>
#include <math.h>
#include <cstdint>

// Problem constants
#define NQ   8192
#define DIM  256
#define NH   8
#define HD   32
#define PP   25
#define HH   512
#define WW   512
#define HWSZ (HH * WW)
#define DFF  1024
#define NHALF (NQ / 2)

// ---------------------------------------------------------------------------
// Scratch (device globals)
// ---------------------------------------------------------------------------
__device__ __nv_bfloat16 g_v_bf[(size_t)NH * HWSZ * HD];  // head-major value tensor
__device__ float g_q[NQ * DIM];
__device__ float g_buf1[NQ * DFF];
__device__ float g_buf2[NQ * DIM];
__device__ float g_smp[NQ * DIM];
__device__ float g_xq[NQ * DIM];
__device__ __nv_bfloat16 g_Wv_bf[DIM * DIM];
__device__ __nv_bfloat16 g_Wo_bf[DIM * DIM];
__device__ __nv_bfloat16 g_W1_bf[DFF * DIM];
__device__ __nv_bfloat16 g_W2_bf[DIM * DFF];
__device__ __nv_bfloat16 g_Wp2_bf[DIM * DIM];
__device__ __nv_bfloat16 g_Wp3_bf[DIM * DIM];
__device__ __nv_bfloat16 g_Wab_hi[DIM * DIM];
__device__ __nv_bfloat16 g_Wab_lo[DIM * DIM];
__device__ float g_bab[DIM];

__device__ __forceinline__ uint32_t smem_to_u32(const void* p) {
    uint32_t a;
    asm("{ .reg .u64 t; cvta.to.shared.u64 t, %1; cvt.u32.u64 %0, t; }" : "=r"(a) : "l"(p));
    return a;
}
#define CP_ASYNC16(dst, src) \
    asm volatile("cp.async.cg.shared.global [%0], [%1], 16;" :: "r"(dst), "l"(src))
#define CP_COMMIT() asm volatile("cp.async.commit_group;" ::: "memory")
#define CP_WAIT0()  asm volatile("cp.async.wait_group 0;" ::: "memory")

#define MBM 128
#define MBN 128
#define MBK 32
#define MSTR 40   // smem row stride: 20 words, 20 % 8 == 4 -> conflict-free ldmatrix

// ---------------------------------------------------------------------------
// 64x128-tile warp-MMA bf16 GEMM — high-occupancy variant.
// EPI: 0=+bias, 1=+bias+relu, 2=+bias+Res
// ---------------------------------------------------------------------------
template <int EPI>
__global__ void __launch_bounds__(256, 3)
mma_gemm64(const float* __restrict__ A, const __nv_bfloat16* __restrict__ B,
           const float* __restrict__ bias, const float* __restrict__ Res,
           float* __restrict__ C, int K, int N) {
    __shared__ __nv_bfloat16 As[64 * MSTR];
    __shared__ __nv_bfloat16 Bs[MBN * MSTR];
    const uint32_t as_base = smem_to_u32(As);
    const uint32_t bs_base = smem_to_u32(Bs);

    const int tid  = threadIdx.x;
    const int wid  = tid >> 5;
    const int lane = tid & 31;
    const int warp_m = wid >> 2;
    const int warp_n = wid & 3;
    const int m0 = blockIdx.y * 64;
    const int n0 = blockIdx.x * MBN;

    float acc[2][4][4];
    #pragma unroll
    for (int i = 0; i < 2; i++)
        #pragma unroll
        for (int j = 0; j < 4; j++)
            #pragma unroll
            for (int r = 0; r < 4; r++) acc[i][j][r] = 0.f;

    const int l16 = lane & 15;
    const uint32_t a_lm_off = (uint32_t)((warp_m * 32 + l16) * MSTR + (lane >> 4) * 8) * 2;
    const uint32_t b_lm_off = (uint32_t)((warp_n * 32 + (l16 & 7)) * MSTR + ((l16 >> 3) * 8)) * 2;

    for (int k0 = 0; k0 < K; k0 += MBK) {
        #pragma unroll
        for (int i = 0; i < 2; i++) {
            int e = i * 256 + tid;
            int r = e >> 3;
            int c = (e & 7) << 2;
            float4 av = *reinterpret_cast<const float4*>(A + (size_t)(m0 + r) * K + k0 + c);
            uint32_t p0, p1;
            asm("cvt.rn.satfinite.bf16x2.f32 %0, %1, %2;" : "=r"(p0) : "f"(av.y), "f"(av.x));
            asm("cvt.rn.satfinite.bf16x2.f32 %0, %1, %2;" : "=r"(p1) : "f"(av.w), "f"(av.z));
            uint32_t addr = as_base + (uint32_t)(r * MSTR + c) * 2;
            asm volatile("st.shared.v2.b32 [%0], {%1, %2};" :: "r"(addr), "r"(p0), "r"(p1));
        }
        #pragma unroll
        for (int i = 0; i < 2; i++) {
            int e = i * 256 + tid;
            int r = e >> 2;
            int c = (e & 3) << 3;
            uint4 bv = *reinterpret_cast<const uint4*>(B + (size_t)(n0 + r) * K + k0 + c);
            uint32_t addr = bs_base + (uint32_t)(r * MSTR + c) * 2;
            asm volatile("st.shared.v4.b32 [%0], {%1, %2, %3, %4};"
                :: "r"(addr), "r"(bv.x), "r"(bv.y), "r"(bv.z), "r"(bv.w));
        }
        __syncthreads();

        #pragma unroll
        for (int ks = 0; ks < 2; ks++) {
            uint32_t af[2][4];
            #pragma unroll
            for (int mt = 0; mt < 2; mt++) {
                uint32_t addr = as_base + a_lm_off + (uint32_t)(mt * 16 * MSTR + ks * 16) * 2;
                asm volatile("ldmatrix.sync.aligned.m8n8.x4.shared.b16 {%0,%1,%2,%3}, [%4];"
                    : "=r"(af[mt][0]), "=r"(af[mt][1]), "=r"(af[mt][2]), "=r"(af[mt][3])
                    : "r"(addr));
            }
            uint32_t bf[4][2];
            #pragma unroll
            for (int nt = 0; nt < 4; nt++) {
                uint32_t addr = bs_base + b_lm_off + (uint32_t)(nt * 8 * MSTR + ks * 16) * 2;
                asm volatile("ldmatrix.sync.aligned.m8n8.x2.shared.b16 {%0,%1}, [%2];"
                    : "=r"(bf[nt][0]), "=r"(bf[nt][1]) : "r"(addr));
            }
            #pragma unroll
            for (int mt = 0; mt < 2; mt++)
                #pragma unroll
                for (int nt = 0; nt < 4; nt++) {
                    asm volatile(
                        "mma.sync.aligned.m16n8k16.row.col.f32.bf16.bf16.f32 "
                        "{%0,%1,%2,%3}, {%4,%5,%6,%7}, {%8,%9}, {%0,%1,%2,%3};"
                        : "+f"(acc[mt][nt][0]), "+f"(acc[mt][nt][1]),
                          "+f"(acc[mt][nt][2]), "+f"(acc[mt][nt][3])
                        : "r"(af[mt][0]), "r"(af[mt][1]), "r"(af[mt][2]), "r"(af[mt][3]),
                          "r"(bf[nt][0]), "r"(bf[nt][1]));
                }
        }
        __syncthreads();
    }

    const int row_in = lane >> 2;
    const int col_in = (lane & 3) << 1;
    #pragma unroll
    for (int mt = 0; mt < 2; mt++) {
        #pragma unroll
        for (int nt = 0; nt < 4; nt++) {
            int n = n0 + warp_n * 32 + nt * 8 + col_in;
            float b0 = bias[n], b1 = bias[n + 1];
            #pragma unroll
            for (int half = 0; half < 2; half++) {
                int m = m0 + warp_m * 32 + mt * 16 + row_in + half * 8;
                float2 o;
                o.x = acc[mt][nt][half * 2 + 0] + b0;
                o.y = acc[mt][nt][half * 2 + 1] + b1;
                if (EPI == 1) { o.x = fmaxf(o.x, 0.f); o.y = fmaxf(o.y, 0.f); }
                if (EPI == 2) {
                    float2 rr = *reinterpret_cast<const float2*>(Res + (size_t)m * N + n);
                    o.x += rr.x; o.y += rr.y;
                }
                *reinterpret_cast<float2*>(C + (size_t)m * N + n) = o;
            }
        }
    }
}

// ---------------------------------------------------------------------------
// 64x128-tile bf16x3 split-precision GEMM (near-fp32) — attn-logits + offsets.
// ---------------------------------------------------------------------------
__global__ void __launch_bounds__(256, 3)
mma_gemm64_x3(const float* __restrict__ A, const __nv_bfloat16* __restrict__ Bhi,
              const __nv_bfloat16* __restrict__ Blo, const float* __restrict__ bias,
              float* __restrict__ C, int K, int N) {
    __shared__ __nv_bfloat16 AsH[64 * MSTR];
    __shared__ __nv_bfloat16 AsL[64 * MSTR];
    __shared__ __nv_bfloat16 BsH[MBN * MSTR];
    __shared__ __nv_bfloat16 BsL[MBN * MSTR];
    const uint32_t ash = smem_to_u32(AsH);
    const uint32_t asl = smem_to_u32(AsL);
    const uint32_t bsh = smem_to_u32(BsH);
    const uint32_t bsl = smem_to_u32(BsL);

    const int tid  = threadIdx.x;
    const int wid  = tid >> 5;
    const int lane = tid & 31;
    const int warp_m = wid >> 2;
    const int warp_n = wid & 3;
    const int m0 = blockIdx.y * 64;
    const int n0 = blockIdx.x * MBN;

    float acc[2][4][4];
    #pragma unroll
    for (int i = 0; i < 2; i++)
        #pragma unroll
        for (int j = 0; j < 4; j++)
            #pragma unroll
            for (int r = 0; r < 4; r++) acc[i][j][r] = 0.f;

    const int l16 = lane & 15;
    const uint32_t a_lm_off = (uint32_t)((warp_m * 32 + l16) * MSTR + (lane >> 4) * 8) * 2;
    const uint32_t b_lm_off = (uint32_t)((warp_n * 32 + (l16 & 7)) * MSTR + ((l16 >> 3) * 8)) * 2;

    for (int k0 = 0; k0 < K; k0 += MBK) {
        #pragma unroll
        for (int i = 0; i < 2; i++) {
            int e = i * 256 + tid;
            int r = e >> 3;
            int c = (e & 7) << 2;
            float4 av = *reinterpret_cast<const float4*>(A + (size_t)(m0 + r) * K + k0 + c);
            __nv_bfloat16 hx = __float2bfloat16(av.x);
            __nv_bfloat16 hy = __float2bfloat16(av.y);
            __nv_bfloat16 hz = __float2bfloat16(av.z);
            __nv_bfloat16 hw = __float2bfloat16(av.w);
            __nv_bfloat162 h01; h01.x = hx; h01.y = hy;
            __nv_bfloat162 h23; h23.x = hz; h23.y = hw;
            uint32_t hp0 = *reinterpret_cast<uint32_t*>(&h01);
            uint32_t hp1 = *reinterpret_cast<uint32_t*>(&h23);
            float lx = av.x - __bfloat162float(hx);
            float ly = av.y - __bfloat162float(hy);
            float lz = av.z - __bfloat162float(hz);
            float lw = av.w - __bfloat162float(hw);
            uint32_t lp0, lp1;
            asm("cvt.rn.satfinite.bf16x2.f32 %0, %1, %2;" : "=r"(lp0) : "f"(ly), "f"(lx));
            asm("cvt.rn.satfinite.bf16x2.f32 %0, %1, %2;" : "=r"(lp1) : "f"(lw), "f"(lz));
            uint32_t off = (uint32_t)(r * MSTR + c) * 2;
            asm volatile("st.shared.v2.b32 [%0], {%1, %2};" :: "r"(ash + off), "r"(hp0), "r"(hp1));
            asm volatile("st.shared.v2.b32 [%0], {%1, %2};" :: "r"(asl + off), "r"(lp0), "r"(lp1));
        }
        #pragma unroll
        for (int i = 0; i < 2; i++) {
            int e = i * 256 + tid;
            int r = e >> 2;
            int c = (e & 3) << 3;
            uint4 bh = *reinterpret_cast<const uint4*>(Bhi + (size_t)(n0 + r) * K + k0 + c);
            uint4 bl = *reinterpret_cast<const uint4*>(Blo + (size_t)(n0 + r) * K + k0 + c);
            uint32_t off = (uint32_t)(r * MSTR + c) * 2;
            asm volatile("st.shared.v4.b32 [%0], {%1, %2, %3, %4};"
                :: "r"(bsh + off), "r"(bh.x), "r"(bh.y), "r"(bh.z), "r"(bh.w));
            asm volatile("st.shared.v4.b32 [%0], {%1, %2, %3, %4};"
                :: "r"(bsl + off), "r"(bl.x), "r"(bl.y), "r"(bl.z), "r"(bl.w));
        }
        __syncthreads();

        #pragma unroll
        for (int pass = 0; pass < 3; pass++) {
            uint32_t abase = (pass == 2) ? asl : ash;
            uint32_t bbase = (pass == 1) ? bsl : bsh;
            #pragma unroll
            for (int ks = 0; ks < 2; ks++) {
                uint32_t af[2][4];
                #pragma unroll
                for (int mt = 0; mt < 2; mt++) {
                    uint32_t addr = abase + a_lm_off + (uint32_t)(mt * 16 * MSTR + ks * 16) * 2;
                    asm volatile("ldmatrix.sync.aligned.m8n8.x4.shared.b16 {%0,%1,%2,%3}, [%4];"
                        : "=r"(af[mt][0]), "=r"(af[mt][1]), "=r"(af[mt][2]), "=r"(af[mt][3])
                        : "r"(addr));
                }
                uint32_t bf[4][2];
                #pragma unroll
                for (int nt = 0; nt < 4; nt++) {
                    uint32_t addr = bbase + b_lm_off + (uint32_t)(nt * 8 * MSTR + ks * 16) * 2;
                    asm volatile("ldmatrix.sync.aligned.m8n8.x2.shared.b16 {%0,%1}, [%2];"
                        : "=r"(bf[nt][0]), "=r"(bf[nt][1]) : "r"(addr));
                }
                #pragma unroll
                for (int mt = 0; mt < 2; mt++)
                    #pragma unroll
                    for (int nt = 0; nt < 4; nt++) {
                        asm volatile(
                            "mma.sync.aligned.m16n8k16.row.col.f32.bf16.bf16.f32 "
                            "{%0,%1,%2,%3}, {%4,%5,%6,%7}, {%8,%9}, {%0,%1,%2,%3};"
                            : "+f"(acc[mt][nt][0]), "+f"(acc[mt][nt][1]),
                              "+f"(acc[mt][nt][2]), "+f"(acc[mt][nt][3])
                            : "r"(af[mt][0]), "r"(af[mt][1]), "r"(af[mt][2]), "r"(af[mt][3]),
                              "r"(bf[nt][0]), "r"(bf[nt][1]));
                    }
            }
        }
        __syncthreads();
    }

    const int row_in = lane >> 2;
    const int col_in = (lane & 3) << 1;
    #pragma unroll
    for (int mt = 0; mt < 2; mt++) {
        #pragma unroll
        for (int nt = 0; nt < 4; nt++) {
            int n = n0 + warp_n * 32 + nt * 8 + col_in;
            float b0 = bias[n], b1 = bias[n + 1];
            #pragma unroll
            for (int half = 0; half < 2; half++) {
                int m = m0 + warp_m * 32 + mt * 16 + row_in + half * 8;
                float2 o;
                o.x = acc[mt][nt][half * 2 + 0] + b0;
                o.y = acc[mt][nt][half * 2 + 1] + b1;
                *reinterpret_cast<float2*>(C + (size_t)m * N + n) = o;
            }
        }
    }
}

// ---------------------------------------------------------------------------
// A-resident K=256 v-projection, M=64 per CTA, cp.async B pipeline.
// Output head-major bf16: v[h][HW][32].  4 CTAs/SM (smem 53KB, regs capped 64).
// ---------------------------------------------------------------------------
#define ASTRIDE 264
#define K256 256
#define VB_BUF (128 * MSTR)
#define KSMEM_TOTAL (64 * ASTRIDE * 2 + 2 * VB_BUF * 2)

__global__ void __launch_bounds__(256, 4)
mma_k256_vproj(const float* __restrict__ A, const __nv_bfloat16* __restrict__ B,
               const float* __restrict__ bias, __nv_bfloat16* __restrict__ VT) {
    extern __shared__ __nv_bfloat16 sm[];
    __nv_bfloat16* As = sm;
    __nv_bfloat16* Bs = sm + 64 * ASTRIDE;
    const uint32_t as_base = smem_to_u32(As);
    const uint32_t bs_base = smem_to_u32(Bs);

    const int tid  = threadIdx.x;
    const int wid  = tid >> 5;
    const int lane = tid & 31;
    const int warp_m = wid >> 2;
    const int warp_n = wid & 3;
    const int m0 = blockIdx.x * 64;

    #pragma unroll
    for (int i = 0; i < 16; i++) {
        int e = i * 256 + tid;
        int r = e >> 6;
        int c = (e & 63) << 2;
        float4 av = *reinterpret_cast<const float4*>(A + (size_t)(m0 + r) * K256 + c);
        uint32_t p0, p1;
        asm("cvt.rn.satfinite.bf16x2.f32 %0, %1, %2;" : "=r"(p0) : "f"(av.y), "f"(av.x));
        asm("cvt.rn.satfinite.bf16x2.f32 %0, %1, %2;" : "=r"(p1) : "f"(av.w), "f"(av.z));
        uint32_t addr = as_base + (uint32_t)(r * ASTRIDE + c) * 2;
        asm volatile("st.shared.v2.b32 [%0], {%1, %2};" :: "r"(addr), "r"(p0), "r"(p1));
    }

    const int l16 = lane & 15;
    const uint32_t a_lm_off = (uint32_t)((warp_m * 32 + l16) * ASTRIDE + (lane >> 4) * 8) * 2;
    const uint32_t b_lm_off = (uint32_t)((warp_n * 32 + (l16 & 7)) * MSTR + ((l16 >> 3) * 8)) * 2;
    const int row_in = lane >> 2;
    const int col_in = (lane & 3) << 1;

    for (int nh = 0; nh < 2; nh++) {
        const int n0 = nh * 128;
        float acc[2][4][4];
        #pragma unroll
        for (int i = 0; i < 2; i++)
            #pragma unroll
            for (int j = 0; j < 4; j++)
                #pragma unroll
                for (int r = 0; r < 4; r++) acc[i][j][r] = 0.f;

        #pragma unroll
        for (int i = 0; i < 2; i++) {
            int e = i * 256 + tid;
            int r = e >> 2;
            int c = (e & 3) << 3;
            uint32_t dst = bs_base + (uint32_t)(r * MSTR + c) * 2;
            const __nv_bfloat16* src = B + (size_t)(n0 + r) * K256 + c;
            CP_ASYNC16(dst, src);
        }
        CP_COMMIT();
        CP_WAIT0();
        __syncthreads();

        for (int ks8 = 0; ks8 < 8; ks8++) {
            int cur = ks8 & 1;
            if (ks8 < 7) {
                uint32_t dbuf = bs_base + (uint32_t)((cur ^ 1) * VB_BUF) * 2;
                #pragma unroll
                for (int i = 0; i < 2; i++) {
                    int e = i * 256 + tid;
                    int r = e >> 2;
                    int c = (e & 3) << 3;
                    uint32_t dst = dbuf + (uint32_t)(r * MSTR + c) * 2;
                    const __nv_bfloat16* src = B + (size_t)(n0 + r) * K256 + (ks8 + 1) * 32 + c;
                    CP_ASYNC16(dst, src);
                }
                CP_COMMIT();
            }
            uint32_t cbuf = bs_base + (uint32_t)(cur * VB_BUF) * 2;
            #pragma unroll
            for (int sub = 0; sub < 2; sub++) {
                int kk = ks8 * 32 + sub * 16;
                uint32_t af[2][4];
                #pragma unroll
                for (int mt = 0; mt < 2; mt++) {
                    uint32_t addr = as_base + a_lm_off + (uint32_t)(mt * 16 * ASTRIDE + kk) * 2;
                    asm volatile("ldmatrix.sync.aligned.m8n8.x4.shared.b16 {%0,%1,%2,%3}, [%4];"
                        : "=r"(af[mt][0]), "=r"(af[mt][1]), "=r"(af[mt][2]), "=r"(af[mt][3])
                        : "r"(addr));
                }
                uint32_t bf[4][2];
                #pragma unroll
                for (int nt = 0; nt < 4; nt++) {
                    uint32_t addr = cbuf + b_lm_off + (uint32_t)(nt * 8 * MSTR + sub * 16) * 2;
                    asm volatile("ldmatrix.sync.aligned.m8n8.x2.shared.b16 {%0,%1}, [%2];"
                        : "=r"(bf[nt][0]), "=r"(bf[nt][1]) : "r"(addr));
                }
                #pragma unroll
                for (int mt = 0; mt < 2; mt++)
                    #pragma unroll
                    for (int nt = 0; nt < 4; nt++) {
                        asm volatile(
                            "mma.sync.aligned.m16n8k16.row.col.f32.bf16.bf16.f32 "
                            "{%0,%1,%2,%3}, {%4,%5,%6,%7}, {%8,%9}, {%0,%1,%2,%3};"
                            : "+f"(acc[mt][nt][0]), "+f"(acc[mt][nt][1]),
                              "+f"(acc[mt][nt][2]), "+f"(acc[mt][nt][3])
                            : "r"(af[mt][0]), "r"(af[mt][1]), "r"(af[mt][2]), "r"(af[mt][3]),
                              "r"(bf[nt][0]), "r"(bf[nt][1]));
                    }
            }
            if (ks8 < 7) { CP_WAIT0(); }
            __syncthreads();
        }

        const int head = nh * 4 + warp_n;
        __nv_bfloat16* vh = VT + (size_t)head * HWSZ * HD;
        #pragma unroll
        for (int mt = 0; mt < 2; mt++) {
            #pragma unroll
            for (int nt = 0; nt < 4; nt++) {
                int ch = nt * 8 + col_in;
                int n = n0 + warp_n * 32 + ch;
                float b0 = bias[n], b1 = bias[n + 1];
                #pragma unroll
                for (int half = 0; half < 2; half++) {
                    int m = m0 + warp_m * 32 + mt * 16 + row_in + half * 8;
                    float ox = acc[mt][nt][half * 2 + 0] + b0;
                    float oy = acc[mt][nt][half * 2 + 1] + b1;
                    uint32_t pr;
                    asm("cvt.rn.satfinite.bf16x2.f32 %0, %1, %2;" : "=r"(pr) : "f"(oy), "f"(ox));
                    *reinterpret_cast<uint32_t*>(vh + (size_t)m * HD + ch) = pr;
                }
            }
        }
        __syncthreads();
    }
}

// ---------------------------------------------------------------------------
// Weight prep
// ---------------------------------------------------------------------------
__global__ void prep_wv(const float* __restrict__ Wv, __nv_bfloat16* __restrict__ dWv) {
    int i = blockIdx.x * 256 + threadIdx.x;
    if (i < DIM * DIM) dWv[i] = __float2bfloat16(Wv[i]);
}

__global__ void prep_rest(const float* __restrict__ Wo,  __nv_bfloat16* __restrict__ dWo,
                          const float* __restrict__ Wp2, __nv_bfloat16* __restrict__ dWp2,
                          const float* __restrict__ Wp3, __nv_bfloat16* __restrict__ dWp3,
                          const float* __restrict__ W1,  __nv_bfloat16* __restrict__ dW1,
                          const float* __restrict__ W2,  __nv_bfloat16* __restrict__ dW2) {
    int i = blockIdx.x * 256 + threadIdx.x;
    const int S = DIM * DIM;
    const int L = DFF * DIM;
    if (i < S)                    dWo[i] = __float2bfloat16(Wo[i]);
    else if (i < 2 * S)           dWp2[i - S] = __float2bfloat16(Wp2[i - S]);
    else if (i < 3 * S)           dWp3[i - 2 * S] = __float2bfloat16(Wp3[i - 2 * S]);
    else if (i < 3 * S + L)       dW1[i - 3 * S] = __float2bfloat16(W1[i - 3 * S]);
    else if (i < 3 * S + 2 * L)   dW2[i - 3 * S - L] = __float2bfloat16(W2[i - 3 * S - L]);
}

__global__ void pack_wab(const float* __restrict__ Wa, const float* __restrict__ Wb,
                         const float* __restrict__ ba, const float* __restrict__ bb,
                         __nv_bfloat16* __restrict__ Whi, __nv_bfloat16* __restrict__ Wlo,
                         float* __restrict__ bab) {
    int row = blockIdx.x;
    int col = threadIdx.x;
    float w = 0.f;
    if (row < 200)      w = Wa[row * DIM + col];
    else if (row < 240) w = Wb[(row - 200) * DIM + col];
    __nv_bfloat16 hi = __float2bfloat16(w);
    Whi[row * DIM + col] = hi;
    Wlo[row * DIM + col] = __float2bfloat16(w - __bfloat162float(hi));
    if (col == 0) {
        float b = 0.f;
        if (row < 200)      b = ba[row];
        else if (row < 240) b = bb[row - 200];
        bab[row] = b;
    }
}

// ---------------------------------------------------------------------------
// fp32 SGEMM (tiny K=8 first pos-MLP layer)
// ---------------------------------------------------------------------------
#define BM 64
#define BN 64
#define BKT 16

__global__ void sgemm_k8_relu(const float* __restrict__ A, const float* __restrict__ B,
                              const float* __restrict__ bias, float* __restrict__ C,
                              int M, int N, int K) {
    __shared__ float As[BKT][BM];
    __shared__ float Bs[BKT][BN];
    const int tid  = threadIdx.x;
    const int brow = blockIdx.y * BM;
    const int bcol = blockIdx.x * BN;
    const int tx = tid & 15;
    const int ty = tid >> 4;
    const int lr = tid >> 2;
    const int lk = (tid & 3) << 2;

    float acc[4][4] = {};
    for (int k0 = 0; k0 < K; k0 += BKT) {
        #pragma unroll
        for (int i = 0; i < 4; i++) {
            int k = k0 + lk + i;
            As[lk + i][lr] = (k < K) ? A[(size_t)(brow + lr) * K + k] : 0.f;
            Bs[lk + i][lr] = (k < K) ? B[(size_t)(bcol + lr) * K + k] : 0.f;
        }
        __syncthreads();
        #pragma unroll
        for (int kk = 0; kk < BKT; kk++) {
            float4 a4 = *reinterpret_cast<const float4*>(&As[kk][ty << 2]);
            float4 b4 = *reinterpret_cast<const float4*>(&Bs[kk][tx << 2]);
            float ar[4] = {a4.x, a4.y, a4.z, a4.w};
            float br[4] = {b4.x, b4.y, b4.z, b4.w};
            #pragma unroll
            for (int i = 0; i < 4; i++)
                #pragma unroll
                for (int j = 0; j < 4; j++)
                    acc[i][j] = fmaf(ar[i], br[j], acc[i][j]);
        }
        __syncthreads();
    }
    #pragma unroll
    for (int i = 0; i < 4; i++) {
        int r = brow + (ty << 2) + i;
        #pragma unroll
        for (int j = 0; j < 4; j++) {
            int c = bcol + (tx << 2) + j;
            C[(size_t)r * N + c] = fmaxf(acc[i][j] + bias[c], 0.f);
        }
    }
}

// ---------------------------------------------------------------------------
// Deformable bilinear sampling v4 — min-instruction gather.
// ---------------------------------------------------------------------------
__global__ void sample_kernel(const float* __restrict__ rw,
                              const float* __restrict__ ao,
                              const __nv_bfloat16* __restrict__ v,
                              float* __restrict__ out) {
    __shared__ float2 s_aw[NH][104];

    int n    = blockIdx.x;
    int h    = threadIdx.x >> 5;
    int lane = threadIdx.x & 31;

    const float* aon = ao + (size_t)n * DIM;
    float logit = (lane < PP) ? aon[h * PP + lane] : -1e30f;
    float mx = logit;
    #pragma unroll
    for (int o = 16; o; o >>= 1) mx = fmaxf(mx, __shfl_xor_sync(0xffffffffu, mx, o));
    float e = (lane < PP) ? expf(logit - mx) : 0.f;
    float s = e;
    #pragma unroll
    for (int o = 16; o; o >>= 1) s += __shfl_xor_sync(0xffffffffu, s, o);
    float myattn = e / s;

    const float* rwn = rw + (size_t)n * 8;
    float rw0 = rwn[0], rw1 = rwn[1], rw3 = rwn[3], rw4 = rwn[4], rw6 = rwn[6];
    const float* offn = aon + 200 + h * 5;
    float o0 = offn[0], o1 = offn[1], o2 = offn[2], o3 = offn[3], o4 = offn[4];

    float cx = rw0 + o0 * 0.125f * rw3;
    float cy = rw1 + o1 * 0.125f * rw4;
    float sx = fmaxf(rw3 + o2 * 0.125f * rw3, 0.f);
    float sy = fmaxf(rw4 + o3 * 0.125f * rw4, 0.f);
    float ang = (rw6 + o4 * (1.0f / 16.0f)) * 6.2831853071795864769f;
    float sth, cth;
    __sincosf(ang, &sth, &cth);

    if (lane < PP) {
        int a = lane / 5, b = lane % 5;
        float gx = sx * (float)(b - 2) * 0.2f;
        float gy = sy * (float)(a - 2) * 0.2f;
        float lx = cx + gx * cth - gy * sth;
        float ly = cy + gx * sth + gy * cth;
        float x = lx * (float)WW - 0.5f;
        float y = ly * (float)HH - 0.5f;
        float x0f = floorf(x), y0f = floorf(y);
        float fx = x - x0f, fy = y - y0f;
        int x0 = (int)x0f, y0 = (int)y0f;
        bool vx0 = (x0 >= 0) && (x0 <= WW - 1);
        bool vx1 = (x0 + 1 >= 0) && (x0 + 1 <= WW - 1);
        bool vy0 = (y0 >= 0) && (y0 <= HH - 1);
        bool vy1 = (y0 + 1 >= 0) && (y0 + 1 <= HH - 1);
        int xc0 = min(max(x0, 0), WW - 1);
        int xc1 = min(max(x0 + 1, 0), WW - 1);
        int yc0 = min(max(y0, 0), HH - 1);
        int yc1 = min(max(y0 + 1, 0), HH - 1);
        float wx0 = 1.f - fx, wx1 = fx;
        float wy0 = 1.f - fy, wy1 = fy;
        float ap = myattn;
        int p4 = lane * 4;
        s_aw[h][p4 + 0] = make_float2(
            __int_as_float((yc0 * WW + xc0) * (HD * 2)),
            (vx0 && vy0) ? (ap * wx0) * wy0 : 0.f);
        s_aw[h][p4 + 1] = make_float2(
            __int_as_float((yc1 * WW + xc0) * (HD * 2)),
            (vx0 && vy1) ? (ap * wx0) * wy1 : 0.f);
        s_aw[h][p4 + 2] = make_float2(
            __int_as_float((yc0 * WW + xc1) * (HD * 2)),
            (vx1 && vy0) ? (ap * wx1) * wy0 : 0.f);
        s_aw[h][p4 + 3] = make_float2(
            __int_as_float((yc1 * WW + xc1) * (HD * 2)),
            (vx1 && vy1) ? (ap * wx1) * wy1 : 0.f);
    } else if (lane < PP + 4) {
        s_aw[h][100 + (lane - PP)] = make_float2(__int_as_float(0), 0.f);
    }
    __syncwarp();

    const char* vb = reinterpret_cast<const char*>(v + (size_t)h * HWSZ * HD);
    const int oct16 = (lane & 3) * 16;
    const int sub   = lane >> 2;
    float acc[8];
    #pragma unroll
    for (int k = 0; k < 8; k++) acc[k] = 0.f;

    #pragma unroll
    for (int r = 0; r < 13; r++) {
        float2 aw = s_aw[h][r * 8 + sub];
        float w = aw.y;
        const uint4* ptr = reinterpret_cast<const uint4*>(
            vb + (size_t)(uint32_t)__float_as_int(aw.x) + oct16);
        uint4 g = *ptr;
        uint32_t gr[4] = {g.x, g.y, g.z, g.w};
        #pragma unroll
        for (int k = 0; k < 4; k++) {
            float flo = __uint_as_float(gr[k] << 16);
            float fhi = __uint_as_float(gr[k] & 0xffff0000u);
            acc[k * 2 + 0] = fmaf(w, flo, acc[k * 2 + 0]);
            acc[k * 2 + 1] = fmaf(w, fhi, acc[k * 2 + 1]);
        }
    }
    #pragma unroll
    for (int k = 0; k < 8; k++) {
        acc[k] += __shfl_xor_sync(0xffffffffu, acc[k], 4);
        acc[k] += __shfl_xor_sync(0xffffffffu, acc[k], 8);
        acc[k] += __shfl_xor_sync(0xffffffffu, acc[k], 16);
    }
    if (sub == 0) {
        float* dst = out + (size_t)n * DIM + h * HD + (lane & 3) * 8;
        float4 w0; w0.x = acc[0]; w0.y = acc[1]; w0.z = acc[2]; w0.w = acc[3];
        float4 w1; w1.x = acc[4]; w1.y = acc[5]; w1.z = acc[6]; w1.w = acc[7];
        *reinterpret_cast<float4*>(dst)     = w0;
        *reinterpret_cast<float4*>(dst + 4) = w1;
    }
}

// ---------------------------------------------------------------------------
// LayerNorm (residual add + LN)
// ---------------------------------------------------------------------------
__global__ void ln_kernel(const float* __restrict__ A, const float* __restrict__ Bb,
                          const float* __restrict__ gamma, const float* __restrict__ beta,
                          float* __restrict__ O) {
    int n = blockIdx.x;
    int c = threadIdx.x;
    float x = A[(size_t)n * DIM + c] + Bb[(size_t)n * DIM + c];
    float s = x, sq = x * x;
    #pragma unroll
    for (int o = 16; o; o >>= 1) {
        s  += __shfl_xor_sync(0xffffffffu, s, o);
        sq += __shfl_xor_sync(0xffffffffu, sq, o);
    }
    __shared__ float sh_s[8], sh_q[8];
    if ((c & 31) == 0) { sh_s[c >> 5] = s; sh_q[c >> 5] = sq; }
    __syncthreads();
    float ts = 0.f, tq = 0.f;
    #pragma unroll
    for (int i = 0; i < 8; i++) { ts += sh_s[i]; tq += sh_q[i]; }
    float mean = ts * (1.0f / (float)DIM);
    float var  = tq * (1.0f / (float)DIM) - mean * mean;
    var = fmaxf(var, 0.f);
    float inv = rsqrtf(var + 1e-5f);
    O[(size_t)n * DIM + c] = (x - mean) * inv * gamma[c] + beta[c];
}

// ---------------------------------------------------------------------------
// Host: tail for one half of the queries on a given stream
// ---------------------------------------------------------------------------
struct TailArgs {
    const float* query; const float* g2; const float* be2;
    const float* g3; const float* be3;
    const float* bo; const float* b1; const float* b2;
    __nv_bfloat16 *Wo_bf, *W1_bf, *W2_bf;
    float *smp, *buf1, *buf2, *xq, *out;
};

static inline void launch_tail_half(const TailArgs& t, int base, cudaStream_t st) {
    const float* q_h   = t.query + (size_t)base * DIM;
    float* smp_h       = t.smp  + (size_t)base * DIM;
    float* buf1_h      = t.buf1 + (size_t)base * DFF;
    float* buf2_h      = t.buf2 + (size_t)base * DIM;
    float* xq_h        = t.xq   + (size_t)base * DIM;
    float* out_h       = t.out  + (size_t)base * DIM;
    mma_gemm64<0><<<dim3(2, NHALF / 64), 256, 0, st>>>(smp_h, t.Wo_bf, t.bo, nullptr, buf2_h, DIM, DIM);
    ln_kernel<<<NHALF, 256, 0, st>>>(q_h, buf2_h, t.g2, t.be2, xq_h);
    mma_gemm64<1><<<dim3(DFF / MBN, NHALF / 64), 256, 0, st>>>(xq_h, t.W1_bf, t.b1, nullptr, buf1_h, DIM, DFF);
    mma_gemm64<0><<<dim3(2, NHALF / 64), 256, 0, st>>>(buf1_h, t.W2_bf, t.b2, nullptr, buf2_h, DFF, DIM);
    ln_kernel<<<NHALF, 256, 0, st>>>(xq_h, buf2_h, t.g3, t.be3, out_h);
}

// ---------------------------------------------------------------------------
// Host orchestration — vproj forked; sample+tail pipelined in query halves.
// ---------------------------------------------------------------------------
extern "C" void kernel_launch(void* const* d_in, const int* in_sizes, int n_in,
                              void* d_out, int out_size) {
    const float* query = (const float*)d_in[0];
    const float* memory = (const float*)d_in[1];
    const float* ref_w  = (const float*)d_in[2];
    const float* Wp1 = (const float*)d_in[5];
    const float* bp1 = (const float*)d_in[6];
    const float* Wp2 = (const float*)d_in[7];
    const float* bp2 = (const float*)d_in[8];
    const float* Wp3 = (const float*)d_in[9];
    const float* bp3 = (const float*)d_in[10];
    const float* Wv  = (const float*)d_in[11];
    const float* bv  = (const float*)d_in[12];
    const float* Wa  = (const float*)d_in[13];
    const float* ba  = (const float*)d_in[14];
    const float* Wb  = (const float*)d_in[15];
    const float* bb  = (const float*)d_in[16];
    const float* Wo  = (const float*)d_in[17];
    const float* bo  = (const float*)d_in[18];
    const float* W1  = (const float*)d_in[19];
    const float* b1  = (const float*)d_in[20];
    const float* W2  = (const float*)d_in[21];
    const float* b2  = (const float*)d_in[22];
    const float* g2  = (const float*)d_in[23];
    const float* be2 = (const float*)d_in[24];
    const float* g3  = (const float*)d_in[25];
    const float* be3 = (const float*)d_in[26];
    float* out = (float*)d_out;

    __nv_bfloat16 *v_bf, *Wv_bf, *Wo_bf, *W1_bf, *W2_bf, *Wp2_bf, *Wp3_bf, *Wab_hi, *Wab_lo;
    float *q, *buf1, *buf2, *smp, *xq, *bab;
    cudaGetSymbolAddress((void**)&v_bf,   g_v_bf);
    cudaGetSymbolAddress((void**)&q,      g_q);
    cudaGetSymbolAddress((void**)&buf1,   g_buf1);
    cudaGetSymbolAddress((void**)&buf2,   g_buf2);
    cudaGetSymbolAddress((void**)&smp,    g_smp);
    cudaGetSymbolAddress((void**)&xq,     g_xq);
    cudaGetSymbolAddress((void**)&Wv_bf,  g_Wv_bf);
    cudaGetSymbolAddress((void**)&Wo_bf,  g_Wo_bf);
    cudaGetSymbolAddress((void**)&W1_bf,  g_W1_bf);
    cudaGetSymbolAddress((void**)&W2_bf,  g_W2_bf);
    cudaGetSymbolAddress((void**)&Wp2_bf, g_Wp2_bf);
    cudaGetSymbolAddress((void**)&Wp3_bf, g_Wp3_bf);
    cudaGetSymbolAddress((void**)&Wab_hi, g_Wab_hi);
    cudaGetSymbolAddress((void**)&Wab_lo, g_Wab_lo);
    cudaGetSymbolAddress((void**)&bab,    g_bab);

    cudaFuncSetAttribute(mma_k256_vproj, cudaFuncAttributeMaxDynamicSharedMemorySize, KSMEM_TOTAL);

    static cudaStream_t s1 = nullptr;
    static cudaEvent_t ev_fork = nullptr, ev_join = nullptr, ev_sa = nullptr, ev_done = nullptr;
    if (s1 == nullptr) {
        cudaStreamCreateWithFlags(&s1, cudaStreamNonBlocking);
        cudaEventCreateWithFlags(&ev_fork, cudaEventDisableTiming);
        cudaEventCreateWithFlags(&ev_join, cudaEventDisableTiming);
        cudaEventCreateWithFlags(&ev_sa,   cudaEventDisableTiming);
        cudaEventCreateWithFlags(&ev_done, cudaEventDisableTiming);
    }

    // (1) Wv conversion — sole gate for vproj
    prep_wv<<<(DIM * DIM + 255) / 256, 256>>>(Wv, Wv_bf);

    // Fork: (2) vproj on side stream
    cudaEventRecord(ev_fork, 0);
    cudaStreamWaitEvent(s1, ev_fork, 0);
    mma_k256_vproj<<<HWSZ / 64, 256, KSMEM_TOTAL, s1>>>(memory, Wv_bf, bv, v_bf);
    cudaEventRecord(ev_join, s1);

    // Main branch (overlaps vproj)
    prep_rest<<<((3 * DIM * DIM + 2 * DFF * DIM) + 255) / 256, 256>>>(
        Wo, Wo_bf, Wp2, Wp2_bf, Wp3, Wp3_bf, W1, W1_bf, W2, W2_bf);
    pack_wab<<<DIM, DIM>>>(Wa, Wb, ba, bb, Wab_hi, Wab_lo, bab);
    sgemm_k8_relu<<<dim3(DIM / BN, NQ / BM), 256>>>(ref_w, Wp1, bp1, buf1, NQ, DIM, 8);
    mma_gemm64<1><<<dim3(2, NQ / 64), 256>>>(buf1, Wp2_bf, bp2, nullptr, buf2, DIM, DIM);
    mma_gemm64<2><<<dim3(2, NQ / 64), 256>>>(buf2, Wp3_bf, bp3, query, q, DIM, DIM);
    mma_gemm64_x3<<<dim3(2, NQ / 64), 256>>>(q, Wab_hi, Wab_lo, bab, buf1, DIM, DIM);

    TailArgs t{query, g2, be2, g3, be3, bo, b1, b2,
               Wo_bf, W1_bf, W2_bf, smp, buf1, buf2, xq, out};

    // Join + pipelined halves:
    //   s0: sampleA -> evSA -> tailA
    //   s1: (wait evSA) sampleB -> tailB  (sampleB overlaps tailA)
    cudaStreamWaitEvent(0, ev_join, 0);
    sample_kernel<<<NHALF, 256>>>(ref_w, buf1, v_bf, smp);
    cudaEventRecord(ev_sa, 0);
    cudaStreamWaitEvent(s1, ev_sa, 0);
    sample_kernel<<<NHALF, 256, 0, s1>>>(
        ref_w + (size_t)NHALF * 8, buf1 + (size_t)NHALF * DIM, v_bf,
        smp + (size_t)NHALF * DIM);
    launch_tail_half(t, 0, 0);
    launch_tail_half(t, NHALF, s1);

    // Join s1 back into the default stream so the graph has a single leaf
    cudaEventRecord(ev_done, s1);
    cudaStreamWaitEvent(0, ev_done, 0);
}

// round 15
// speedup vs baseline: 1.0387x; 1.0387x over previous
#include <cuda_runtime.h>
#include <cuda_bf16.h>
#include <math.h>
#include <cstdint>

// Problem constants
#define NQ   8192
#define DIM  256
#define NH   8
#define HD   32
#define PP   25
#define HH   512
#define WW   512
#define HWSZ (HH * WW)
#define DFF  1024
#define NHALF (NQ / 2)

// ---------------------------------------------------------------------------
// Scratch (device globals)
// ---------------------------------------------------------------------------
__device__ __nv_bfloat16 g_v_bf[(size_t)NH * HWSZ * HD];  // head-major value tensor
__device__ float g_q[NQ * DIM];
__device__ float g_buf1[NQ * DFF];
__device__ float g_buf2[NQ * DIM];
__device__ float g_smp[NQ * DIM];
__device__ float g_xq[NQ * DIM];
__device__ __nv_bfloat16 g_Wv_bf[DIM * DIM];
__device__ __nv_bfloat16 g_Wo_bf[DIM * DIM];
__device__ __nv_bfloat16 g_W1_bf[DFF * DIM];
__device__ __nv_bfloat16 g_W2_bf[DIM * DFF];
__device__ __nv_bfloat16 g_Wp2_bf[DIM * DIM];
__device__ __nv_bfloat16 g_Wp3_bf[DIM * DIM];
__device__ __nv_bfloat16 g_Wab_hi[DIM * DIM];
__device__ __nv_bfloat16 g_Wab_lo[DIM * DIM];
__device__ float g_bab[DIM];

__device__ __forceinline__ uint32_t smem_to_u32(const void* p) {
    uint32_t a;
    asm("{ .reg .u64 t; cvta.to.shared.u64 t, %1; cvt.u32.u64 %0, t; }" : "=r"(a) : "l"(p));
    return a;
}
#define CP_ASYNC16(dst, src) \
    asm volatile("cp.async.cg.shared.global [%0], [%1], 16;" :: "r"(dst), "l"(src))
#define CP_COMMIT() asm volatile("cp.async.commit_group;" ::: "memory")
#define CP_WAIT0()  asm volatile("cp.async.wait_group 0;" ::: "memory")

#define MBM 128
#define MBN 128
#define MBK 32
#define MSTR 40   // smem row stride: 20 words, 20 % 8 == 4 -> conflict-free ldmatrix

// ---------------------------------------------------------------------------
// 64x128-tile warp-MMA bf16 GEMM — high-occupancy variant.
// EPI: 0=+bias, 1=+bias+relu, 2=+bias+Res
// ---------------------------------------------------------------------------
template <int EPI>
__global__ void __launch_bounds__(256, 3)
mma_gemm64(const float* __restrict__ A, const __nv_bfloat16* __restrict__ B,
           const float* __restrict__ bias, const float* __restrict__ Res,
           float* __restrict__ C, int K, int N) {
    __shared__ __nv_bfloat16 As[64 * MSTR];
    __shared__ __nv_bfloat16 Bs[MBN * MSTR];
    const uint32_t as_base = smem_to_u32(As);
    const uint32_t bs_base = smem_to_u32(Bs);

    const int tid  = threadIdx.x;
    const int wid  = tid >> 5;
    const int lane = tid & 31;
    const int warp_m = wid >> 2;
    const int warp_n = wid & 3;
    const int m0 = blockIdx.y * 64;
    const int n0 = blockIdx.x * MBN;

    float acc[2][4][4];
    #pragma unroll
    for (int i = 0; i < 2; i++)
        #pragma unroll
        for (int j = 0; j < 4; j++)
            #pragma unroll
            for (int r = 0; r < 4; r++) acc[i][j][r] = 0.f;

    const int l16 = lane & 15;
    const uint32_t a_lm_off = (uint32_t)((warp_m * 32 + l16) * MSTR + (lane >> 4) * 8) * 2;
    const uint32_t b_lm_off = (uint32_t)((warp_n * 32 + (l16 & 7)) * MSTR + ((l16 >> 3) * 8)) * 2;

    for (int k0 = 0; k0 < K; k0 += MBK) {
        #pragma unroll
        for (int i = 0; i < 2; i++) {
            int e = i * 256 + tid;
            int r = e >> 3;
            int c = (e & 7) << 2;
            float4 av = *reinterpret_cast<const float4*>(A + (size_t)(m0 + r) * K + k0 + c);
            uint32_t p0, p1;
            asm("cvt.rn.satfinite.bf16x2.f32 %0, %1, %2;" : "=r"(p0) : "f"(av.y), "f"(av.x));
            asm("cvt.rn.satfinite.bf16x2.f32 %0, %1, %2;" : "=r"(p1) : "f"(av.w), "f"(av.z));
            uint32_t addr = as_base + (uint32_t)(r * MSTR + c) * 2;
            asm volatile("st.shared.v2.b32 [%0], {%1, %2};" :: "r"(addr), "r"(p0), "r"(p1));
        }
        #pragma unroll
        for (int i = 0; i < 2; i++) {
            int e = i * 256 + tid;
            int r = e >> 2;
            int c = (e & 3) << 3;
            uint4 bv = *reinterpret_cast<const uint4*>(B + (size_t)(n0 + r) * K + k0 + c);
            uint32_t addr = bs_base + (uint32_t)(r * MSTR + c) * 2;
            asm volatile("st.shared.v4.b32 [%0], {%1, %2, %3, %4};"
                :: "r"(addr), "r"(bv.x), "r"(bv.y), "r"(bv.z), "r"(bv.w));
        }
        __syncthreads();

        #pragma unroll
        for (int ks = 0; ks < 2; ks++) {
            uint32_t af[2][4];
            #pragma unroll
            for (int mt = 0; mt < 2; mt++) {
                uint32_t addr = as_base + a_lm_off + (uint32_t)(mt * 16 * MSTR + ks * 16) * 2;
                asm volatile("ldmatrix.sync.aligned.m8n8.x4.shared.b16 {%0,%1,%2,%3}, [%4];"
                    : "=r"(af[mt][0]), "=r"(af[mt][1]), "=r"(af[mt][2]), "=r"(af[mt][3])
                    : "r"(addr));
            }
            uint32_t bf[4][2];
            #pragma unroll
            for (int nt = 0; nt < 4; nt++) {
                uint32_t addr = bs_base + b_lm_off + (uint32_t)(nt * 8 * MSTR + ks * 16) * 2;
                asm volatile("ldmatrix.sync.aligned.m8n8.x2.shared.b16 {%0,%1}, [%2];"
                    : "=r"(bf[nt][0]), "=r"(bf[nt][1]) : "r"(addr));
            }
            #pragma unroll
            for (int mt = 0; mt < 2; mt++)
                #pragma unroll
                for (int nt = 0; nt < 4; nt++) {
                    asm volatile(
                        "mma.sync.aligned.m16n8k16.row.col.f32.bf16.bf16.f32 "
                        "{%0,%1,%2,%3}, {%4,%5,%6,%7}, {%8,%9}, {%0,%1,%2,%3};"
                        : "+f"(acc[mt][nt][0]), "+f"(acc[mt][nt][1]),
                          "+f"(acc[mt][nt][2]), "+f"(acc[mt][nt][3])
                        : "r"(af[mt][0]), "r"(af[mt][1]), "r"(af[mt][2]), "r"(af[mt][3]),
                          "r"(bf[nt][0]), "r"(bf[nt][1]));
                }
        }
        __syncthreads();
    }

    const int row_in = lane >> 2;
    const int col_in = (lane & 3) << 1;
    #pragma unroll
    for (int mt = 0; mt < 2; mt++) {
        #pragma unroll
        for (int nt = 0; nt < 4; nt++) {
            int n = n0 + warp_n * 32 + nt * 8 + col_in;
            float b0 = bias[n], b1 = bias[n + 1];
            #pragma unroll
            for (int half = 0; half < 2; half++) {
                int m = m0 + warp_m * 32 + mt * 16 + row_in + half * 8;
                float2 o;
                o.x = acc[mt][nt][half * 2 + 0] + b0;
                o.y = acc[mt][nt][half * 2 + 1] + b1;
                if (EPI == 1) { o.x = fmaxf(o.x, 0.f); o.y = fmaxf(o.y, 0.f); }
                if (EPI == 2) {
                    float2 rr = *reinterpret_cast<const float2*>(Res + (size_t)m * N + n);
                    o.x += rr.x; o.y += rr.y;
                }
                *reinterpret_cast<float2*>(C + (size_t)m * N + n) = o;
            }
        }
    }
}

// ---------------------------------------------------------------------------
// 64x128-tile bf16x3 split-precision GEMM (near-fp32) — attn-logits + offsets.
// ---------------------------------------------------------------------------
__global__ void __launch_bounds__(256, 3)
mma_gemm64_x3(const float* __restrict__ A, const __nv_bfloat16* __restrict__ Bhi,
              const __nv_bfloat16* __restrict__ Blo, const float* __restrict__ bias,
              float* __restrict__ C, int K, int N) {
    __shared__ __nv_bfloat16 AsH[64 * MSTR];
    __shared__ __nv_bfloat16 AsL[64 * MSTR];
    __shared__ __nv_bfloat16 BsH[MBN * MSTR];
    __shared__ __nv_bfloat16 BsL[MBN * MSTR];
    const uint32_t ash = smem_to_u32(AsH);
    const uint32_t asl = smem_to_u32(AsL);
    const uint32_t bsh = smem_to_u32(BsH);
    const uint32_t bsl = smem_to_u32(BsL);

    const int tid  = threadIdx.x;
    const int wid  = tid >> 5;
    const int lane = tid & 31;
    const int warp_m = wid >> 2;
    const int warp_n = wid & 3;
    const int m0 = blockIdx.y * 64;
    const int n0 = blockIdx.x * MBN;

    float acc[2][4][4];
    #pragma unroll
    for (int i = 0; i < 2; i++)
        #pragma unroll
        for (int j = 0; j < 4; j++)
            #pragma unroll
            for (int r = 0; r < 4; r++) acc[i][j][r] = 0.f;

    const int l16 = lane & 15;
    const uint32_t a_lm_off = (uint32_t)((warp_m * 32 + l16) * MSTR + (lane >> 4) * 8) * 2;
    const uint32_t b_lm_off = (uint32_t)((warp_n * 32 + (l16 & 7)) * MSTR + ((l16 >> 3) * 8)) * 2;

    for (int k0 = 0; k0 < K; k0 += MBK) {
        #pragma unroll
        for (int i = 0; i < 2; i++) {
            int e = i * 256 + tid;
            int r = e >> 3;
            int c = (e & 7) << 2;
            float4 av = *reinterpret_cast<const float4*>(A + (size_t)(m0 + r) * K + k0 + c);
            __nv_bfloat16 hx = __float2bfloat16(av.x);
            __nv_bfloat16 hy = __float2bfloat16(av.y);
            __nv_bfloat16 hz = __float2bfloat16(av.z);
            __nv_bfloat16 hw = __float2bfloat16(av.w);
            __nv_bfloat162 h01; h01.x = hx; h01.y = hy;
            __nv_bfloat162 h23; h23.x = hz; h23.y = hw;
            uint32_t hp0 = *reinterpret_cast<uint32_t*>(&h01);
            uint32_t hp1 = *reinterpret_cast<uint32_t*>(&h23);
            float lx = av.x - __bfloat162float(hx);
            float ly = av.y - __bfloat162float(hy);
            float lz = av.z - __bfloat162float(hz);
            float lw = av.w - __bfloat162float(hw);
            uint32_t lp0, lp1;
            asm("cvt.rn.satfinite.bf16x2.f32 %0, %1, %2;" : "=r"(lp0) : "f"(ly), "f"(lx));
            asm("cvt.rn.satfinite.bf16x2.f32 %0, %1, %2;" : "=r"(lp1) : "f"(lw), "f"(lz));
            uint32_t off = (uint32_t)(r * MSTR + c) * 2;
            asm volatile("st.shared.v2.b32 [%0], {%1, %2};" :: "r"(ash + off), "r"(hp0), "r"(hp1));
            asm volatile("st.shared.v2.b32 [%0], {%1, %2};" :: "r"(asl + off), "r"(lp0), "r"(lp1));
        }
        #pragma unroll
        for (int i = 0; i < 2; i++) {
            int e = i * 256 + tid;
            int r = e >> 2;
            int c = (e & 3) << 3;
            uint4 bh = *reinterpret_cast<const uint4*>(Bhi + (size_t)(n0 + r) * K + k0 + c);
            uint4 bl = *reinterpret_cast<const uint4*>(Blo + (size_t)(n0 + r) * K + k0 + c);
            uint32_t off = (uint32_t)(r * MSTR + c) * 2;
            asm volatile("st.shared.v4.b32 [%0], {%1, %2, %3, %4};"
                :: "r"(bsh + off), "r"(bh.x), "r"(bh.y), "r"(bh.z), "r"(bh.w));
            asm volatile("st.shared.v4.b32 [%0], {%1, %2, %3, %4};"
                :: "r"(bsl + off), "r"(bl.x), "r"(bl.y), "r"(bl.z), "r"(bl.w));
        }
        __syncthreads();

        #pragma unroll
        for (int pass = 0; pass < 3; pass++) {
            uint32_t abase = (pass == 2) ? asl : ash;
            uint32_t bbase = (pass == 1) ? bsl : bsh;
            #pragma unroll
            for (int ks = 0; ks < 2; ks++) {
                uint32_t af[2][4];
                #pragma unroll
                for (int mt = 0; mt < 2; mt++) {
                    uint32_t addr = abase + a_lm_off + (uint32_t)(mt * 16 * MSTR + ks * 16) * 2;
                    asm volatile("ldmatrix.sync.aligned.m8n8.x4.shared.b16 {%0,%1,%2,%3}, [%4];"
                        : "=r"(af[mt][0]), "=r"(af[mt][1]), "=r"(af[mt][2]), "=r"(af[mt][3])
                        : "r"(addr));
                }
                uint32_t bf[4][2];
                #pragma unroll
                for (int nt = 0; nt < 4; nt++) {
                    uint32_t addr = bbase + b_lm_off + (uint32_t)(nt * 8 * MSTR + ks * 16) * 2;
                    asm volatile("ldmatrix.sync.aligned.m8n8.x2.shared.b16 {%0,%1}, [%2];"
                        : "=r"(bf[nt][0]), "=r"(bf[nt][1]) : "r"(addr));
                }
                #pragma unroll
                for (int mt = 0; mt < 2; mt++)
                    #pragma unroll
                    for (int nt = 0; nt < 4; nt++) {
                        asm volatile(
                            "mma.sync.aligned.m16n8k16.row.col.f32.bf16.bf16.f32 "
                            "{%0,%1,%2,%3}, {%4,%5,%6,%7}, {%8,%9}, {%0,%1,%2,%3};"
                            : "+f"(acc[mt][nt][0]), "+f"(acc[mt][nt][1]),
                              "+f"(acc[mt][nt][2]), "+f"(acc[mt][nt][3])
                            : "r"(af[mt][0]), "r"(af[mt][1]), "r"(af[mt][2]), "r"(af[mt][3]),
                              "r"(bf[nt][0]), "r"(bf[nt][1]));
                    }
            }
        }
        __syncthreads();
    }

    const int row_in = lane >> 2;
    const int col_in = (lane & 3) << 1;
    #pragma unroll
    for (int mt = 0; mt < 2; mt++) {
        #pragma unroll
        for (int nt = 0; nt < 4; nt++) {
            int n = n0 + warp_n * 32 + nt * 8 + col_in;
            float b0 = bias[n], b1 = bias[n + 1];
            #pragma unroll
            for (int half = 0; half < 2; half++) {
                int m = m0 + warp_m * 32 + mt * 16 + row_in + half * 8;
                float2 o;
                o.x = acc[mt][nt][half * 2 + 0] + b0;
                o.y = acc[mt][nt][half * 2 + 1] + b1;
                *reinterpret_cast<float2*>(C + (size_t)m * N + n) = o;
            }
        }
    }
}

// ---------------------------------------------------------------------------
// A-resident K=256 v-projection, M=64 per CTA, cp.async B pipeline.
// Output head-major bf16: v[h][HW][32].  3 CTAs/SM (R13-proven, no spills).
// ---------------------------------------------------------------------------
#define ASTRIDE 264
#define K256 256
#define VB_BUF (128 * MSTR)
#define KSMEM_TOTAL (64 * ASTRIDE * 2 + 2 * VB_BUF * 2)

__global__ void __launch_bounds__(256, 3)
mma_k256_vproj(const float* __restrict__ A, const __nv_bfloat16* __restrict__ B,
               const float* __restrict__ bias, __nv_bfloat16* __restrict__ VT) {
    extern __shared__ __nv_bfloat16 sm[];
    __nv_bfloat16* As = sm;
    __nv_bfloat16* Bs = sm + 64 * ASTRIDE;
    const uint32_t as_base = smem_to_u32(As);
    const uint32_t bs_base = smem_to_u32(Bs);

    const int tid  = threadIdx.x;
    const int wid  = tid >> 5;
    const int lane = tid & 31;
    const int warp_m = wid >> 2;
    const int warp_n = wid & 3;
    const int m0 = blockIdx.x * 64;

    #pragma unroll
    for (int i = 0; i < 16; i++) {
        int e = i * 256 + tid;
        int r = e >> 6;
        int c = (e & 63) << 2;
        float4 av = *reinterpret_cast<const float4*>(A + (size_t)(m0 + r) * K256 + c);
        uint32_t p0, p1;
        asm("cvt.rn.satfinite.bf16x2.f32 %0, %1, %2;" : "=r"(p0) : "f"(av.y), "f"(av.x));
        asm("cvt.rn.satfinite.bf16x2.f32 %0, %1, %2;" : "=r"(p1) : "f"(av.w), "f"(av.z));
        uint32_t addr = as_base + (uint32_t)(r * ASTRIDE + c) * 2;
        asm volatile("st.shared.v2.b32 [%0], {%1, %2};" :: "r"(addr), "r"(p0), "r"(p1));
    }

    const int l16 = lane & 15;
    const uint32_t a_lm_off = (uint32_t)((warp_m * 32 + l16) * ASTRIDE + (lane >> 4) * 8) * 2;
    const uint32_t b_lm_off = (uint32_t)((warp_n * 32 + (l16 & 7)) * MSTR + ((l16 >> 3) * 8)) * 2;
    const int row_in = lane >> 2;
    const int col_in = (lane & 3) << 1;

    for (int nh = 0; nh < 2; nh++) {
        const int n0 = nh * 128;
        float acc[2][4][4];
        #pragma unroll
        for (int i = 0; i < 2; i++)
            #pragma unroll
            for (int j = 0; j < 4; j++)
                #pragma unroll
                for (int r = 0; r < 4; r++) acc[i][j][r] = 0.f;

        #pragma unroll
        for (int i = 0; i < 2; i++) {
            int e = i * 256 + tid;
            int r = e >> 2;
            int c = (e & 3) << 3;
            uint32_t dst = bs_base + (uint32_t)(r * MSTR + c) * 2;
            const __nv_bfloat16* src = B + (size_t)(n0 + r) * K256 + c;
            CP_ASYNC16(dst, src);
        }
        CP_COMMIT();
        CP_WAIT0();
        __syncthreads();

        for (int ks8 = 0; ks8 < 8; ks8++) {
            int cur = ks8 & 1;
            if (ks8 < 7) {
                uint32_t dbuf = bs_base + (uint32_t)((cur ^ 1) * VB_BUF) * 2;
                #pragma unroll
                for (int i = 0; i < 2; i++) {
                    int e = i * 256 + tid;
                    int r = e >> 2;
                    int c = (e & 3) << 3;
                    uint32_t dst = dbuf + (uint32_t)(r * MSTR + c) * 2;
                    const __nv_bfloat16* src = B + (size_t)(n0 + r) * K256 + (ks8 + 1) * 32 + c;
                    CP_ASYNC16(dst, src);
                }
                CP_COMMIT();
            }
            uint32_t cbuf = bs_base + (uint32_t)(cur * VB_BUF) * 2;
            #pragma unroll
            for (int sub = 0; sub < 2; sub++) {
                int kk = ks8 * 32 + sub * 16;
                uint32_t af[2][4];
                #pragma unroll
                for (int mt = 0; mt < 2; mt++) {
                    uint32_t addr = as_base + a_lm_off + (uint32_t)(mt * 16 * ASTRIDE + kk) * 2;
                    asm volatile("ldmatrix.sync.aligned.m8n8.x4.shared.b16 {%0,%1,%2,%3}, [%4];"
                        : "=r"(af[mt][0]), "=r"(af[mt][1]), "=r"(af[mt][2]), "=r"(af[mt][3])
                        : "r"(addr));
                }
                uint32_t bf[4][2];
                #pragma unroll
                for (int nt = 0; nt < 4; nt++) {
                    uint32_t addr = cbuf + b_lm_off + (uint32_t)(nt * 8 * MSTR + sub * 16) * 2;
                    asm volatile("ldmatrix.sync.aligned.m8n8.x2.shared.b16 {%0,%1}, [%2];"
                        : "=r"(bf[nt][0]), "=r"(bf[nt][1]) : "r"(addr));
                }
                #pragma unroll
                for (int mt = 0; mt < 2; mt++)
                    #pragma unroll
                    for (int nt = 0; nt < 4; nt++) {
                        asm volatile(
                            "mma.sync.aligned.m16n8k16.row.col.f32.bf16.bf16.f32 "
                            "{%0,%1,%2,%3}, {%4,%5,%6,%7}, {%8,%9}, {%0,%1,%2,%3};"
                            : "+f"(acc[mt][nt][0]), "+f"(acc[mt][nt][1]),
                              "+f"(acc[mt][nt][2]), "+f"(acc[mt][nt][3])
                            : "r"(af[mt][0]), "r"(af[mt][1]), "r"(af[mt][2]), "r"(af[mt][3]),
                              "r"(bf[nt][0]), "r"(bf[nt][1]));
                    }
            }
            if (ks8 < 7) { CP_WAIT0(); }
            __syncthreads();
        }

        const int head = nh * 4 + warp_n;
        __nv_bfloat16* vh = VT + (size_t)head * HWSZ * HD;
        #pragma unroll
        for (int mt = 0; mt < 2; mt++) {
            #pragma unroll
            for (int nt = 0; nt < 4; nt++) {
                int ch = nt * 8 + col_in;
                int n = n0 + warp_n * 32 + ch;
                float b0 = bias[n], b1 = bias[n + 1];
                #pragma unroll
                for (int half = 0; half < 2; half++) {
                    int m = m0 + warp_m * 32 + mt * 16 + row_in + half * 8;
                    float ox = acc[mt][nt][half * 2 + 0] + b0;
                    float oy = acc[mt][nt][half * 2 + 1] + b1;
                    uint32_t pr;
                    asm("cvt.rn.satfinite.bf16x2.f32 %0, %1, %2;" : "=r"(pr) : "f"(oy), "f"(ox));
                    *reinterpret_cast<uint32_t*>(vh + (size_t)m * HD + ch) = pr;
                }
            }
        }
        __syncthreads();
    }
}

// ---------------------------------------------------------------------------
// Weight prep
// ---------------------------------------------------------------------------
__global__ void prep_wv(const float* __restrict__ Wv, __nv_bfloat16* __restrict__ dWv) {
    int i = blockIdx.x * 256 + threadIdx.x;
    if (i < DIM * DIM) dWv[i] = __float2bfloat16(Wv[i]);
}

__global__ void prep_rest(const float* __restrict__ Wo,  __nv_bfloat16* __restrict__ dWo,
                          const float* __restrict__ Wp2, __nv_bfloat16* __restrict__ dWp2,
                          const float* __restrict__ Wp3, __nv_bfloat16* __restrict__ dWp3,
                          const float* __restrict__ W1,  __nv_bfloat16* __restrict__ dW1,
                          const float* __restrict__ W2,  __nv_bfloat16* __restrict__ dW2) {
    int i = blockIdx.x * 256 + threadIdx.x;
    const int S = DIM * DIM;
    const int L = DFF * DIM;
    if (i < S)                    dWo[i] = __float2bfloat16(Wo[i]);
    else if (i < 2 * S)           dWp2[i - S] = __float2bfloat16(Wp2[i - S]);
    else if (i < 3 * S)           dWp3[i - 2 * S] = __float2bfloat16(Wp3[i - 2 * S]);
    else if (i < 3 * S + L)       dW1[i - 3 * S] = __float2bfloat16(W1[i - 3 * S]);
    else if (i < 3 * S + 2 * L)   dW2[i - 3 * S - L] = __float2bfloat16(W2[i - 3 * S - L]);
}

__global__ void pack_wab(const float* __restrict__ Wa, const float* __restrict__ Wb,
                         const float* __restrict__ ba, const float* __restrict__ bb,
                         __nv_bfloat16* __restrict__ Whi, __nv_bfloat16* __restrict__ Wlo,
                         float* __restrict__ bab) {
    int row = blockIdx.x;
    int col = threadIdx.x;
    float w = 0.f;
    if (row < 200)      w = Wa[row * DIM + col];
    else if (row < 240) w = Wb[(row - 200) * DIM + col];
    __nv_bfloat16 hi = __float2bfloat16(w);
    Whi[row * DIM + col] = hi;
    Wlo[row * DIM + col] = __float2bfloat16(w - __bfloat162float(hi));
    if (col == 0) {
        float b = 0.f;
        if (row < 200)      b = ba[row];
        else if (row < 240) b = bb[row - 200];
        bab[row] = b;
    }
}

// ---------------------------------------------------------------------------
// fp32 SGEMM (tiny K=8 first pos-MLP layer)
// ---------------------------------------------------------------------------
#define BM 64
#define BN 64
#define BKT 16

__global__ void sgemm_k8_relu(const float* __restrict__ A, const float* __restrict__ B,
                              const float* __restrict__ bias, float* __restrict__ C,
                              int M, int N, int K) {
    __shared__ float As[BKT][BM];
    __shared__ float Bs[BKT][BN];
    const int tid  = threadIdx.x;
    const int brow = blockIdx.y * BM;
    const int bcol = blockIdx.x * BN;
    const int tx = tid & 15;
    const int ty = tid >> 4;
    const int lr = tid >> 2;
    const int lk = (tid & 3) << 2;

    float acc[4][4] = {};
    for (int k0 = 0; k0 < K; k0 += BKT) {
        #pragma unroll
        for (int i = 0; i < 4; i++) {
            int k = k0 + lk + i;
            As[lk + i][lr] = (k < K) ? A[(size_t)(brow + lr) * K + k] : 0.f;
            Bs[lk + i][lr] = (k < K) ? B[(size_t)(bcol + lr) * K + k] : 0.f;
        }
        __syncthreads();
        #pragma unroll
        for (int kk = 0; kk < BKT; kk++) {
            float4 a4 = *reinterpret_cast<const float4*>(&As[kk][ty << 2]);
            float4 b4 = *reinterpret_cast<const float4*>(&Bs[kk][tx << 2]);
            float ar[4] = {a4.x, a4.y, a4.z, a4.w};
            float br[4] = {b4.x, b4.y, b4.z, b4.w};
            #pragma unroll
            for (int i = 0; i < 4; i++)
                #pragma unroll
                for (int j = 0; j < 4; j++)
                    acc[i][j] = fmaf(ar[i], br[j], acc[i][j]);
        }
        __syncthreads();
    }
    #pragma unroll
    for (int i = 0; i < 4; i++) {
        int r = brow + (ty << 2) + i;
        #pragma unroll
        for (int j = 0; j < 4; j++) {
            int c = bcol + (tx << 2) + j;
            C[(size_t)r * N + c] = fmaxf(acc[i][j] + bias[c], 0.f);
        }
    }
}

// ---------------------------------------------------------------------------
// Deformable bilinear sampling v4 — min-instruction gather.
// ---------------------------------------------------------------------------
__global__ void sample_kernel(const float* __restrict__ rw,
                              const float* __restrict__ ao,
                              const __nv_bfloat16* __restrict__ v,
                              float* __restrict__ out) {
    __shared__ float2 s_aw[NH][104];

    int n    = blockIdx.x;
    int h    = threadIdx.x >> 5;
    int lane = threadIdx.x & 31;

    const float* aon = ao + (size_t)n * DIM;
    float logit = (lane < PP) ? aon[h * PP + lane] : -1e30f;
    float mx = logit;
    #pragma unroll
    for (int o = 16; o; o >>= 1) mx = fmaxf(mx, __shfl_xor_sync(0xffffffffu, mx, o));
    float e = (lane < PP) ? expf(logit - mx) : 0.f;
    float s = e;
    #pragma unroll
    for (int o = 16; o; o >>= 1) s += __shfl_xor_sync(0xffffffffu, s, o);
    float myattn = e / s;

    const float* rwn = rw + (size_t)n * 8;
    float rw0 = rwn[0], rw1 = rwn[1], rw3 = rwn[3], rw4 = rwn[4], rw6 = rwn[6];
    const float* offn = aon + 200 + h * 5;
    float o0 = offn[0], o1 = offn[1], o2 = offn[2], o3 = offn[3], o4 = offn[4];

    float cx = rw0 + o0 * 0.125f * rw3;
    float cy = rw1 + o1 * 0.125f * rw4;
    float sx = fmaxf(rw3 + o2 * 0.125f * rw3, 0.f);
    float sy = fmaxf(rw4 + o3 * 0.125f * rw4, 0.f);
    float ang = (rw6 + o4 * (1.0f / 16.0f)) * 6.2831853071795864769f;
    float sth, cth;
    __sincosf(ang, &sth, &cth);

    if (lane < PP) {
        int a = lane / 5, b = lane % 5;
        float gx = sx * (float)(b - 2) * 0.2f;
        float gy = sy * (float)(a - 2) * 0.2f;
        float lx = cx + gx * cth - gy * sth;
        float ly = cy + gx * sth + gy * cth;
        float x = lx * (float)WW - 0.5f;
        float y = ly * (float)HH - 0.5f;
        float x0f = floorf(x), y0f = floorf(y);
        float fx = x - x0f, fy = y - y0f;
        int x0 = (int)x0f, y0 = (int)y0f;
        bool vx0 = (x0 >= 0) && (x0 <= WW - 1);
        bool vx1 = (x0 + 1 >= 0) && (x0 + 1 <= WW - 1);
        bool vy0 = (y0 >= 0) && (y0 <= HH - 1);
        bool vy1 = (y0 + 1 >= 0) && (y0 + 1 <= HH - 1);
        int xc0 = min(max(x0, 0), WW - 1);
        int xc1 = min(max(x0 + 1, 0), WW - 1);
        int yc0 = min(max(y0, 0), HH - 1);
        int yc1 = min(max(y0 + 1, 0), HH - 1);
        float wx0 = 1.f - fx, wx1 = fx;
        float wy0 = 1.f - fy, wy1 = fy;
        float ap = myattn;
        int p4 = lane * 4;
        s_aw[h][p4 + 0] = make_float2(
            __int_as_float((yc0 * WW + xc0) * (HD * 2)),
            (vx0 && vy0) ? (ap * wx0) * wy0 : 0.f);
        s_aw[h][p4 + 1] = make_float2(
            __int_as_float((yc1 * WW + xc0) * (HD * 2)),
            (vx0 && vy1) ? (ap * wx0) * wy1 : 0.f);
        s_aw[h][p4 + 2] = make_float2(
            __int_as_float((yc0 * WW + xc1) * (HD * 2)),
            (vx1 && vy0) ? (ap * wx1) * wy0 : 0.f);
        s_aw[h][p4 + 3] = make_float2(
            __int_as_float((yc1 * WW + xc1) * (HD * 2)),
            (vx1 && vy1) ? (ap * wx1) * wy1 : 0.f);
    } else if (lane < PP + 4) {
        s_aw[h][100 + (lane - PP)] = make_float2(__int_as_float(0), 0.f);
    }
    __syncwarp();

    const char* vb = reinterpret_cast<const char*>(v + (size_t)h * HWSZ * HD);
    const int oct16 = (lane & 3) * 16;
    const int sub   = lane >> 2;
    float acc[8];
    #pragma unroll
    for (int k = 0; k < 8; k++) acc[k] = 0.f;

    #pragma unroll
    for (int r = 0; r < 13; r++) {
        float2 aw = s_aw[h][r * 8 + sub];
        float w = aw.y;
        const uint4* ptr = reinterpret_cast<const uint4*>(
            vb + (size_t)(uint32_t)__float_as_int(aw.x) + oct16);
        uint4 g = *ptr;
        uint32_t gr[4] = {g.x, g.y, g.z, g.w};
        #pragma unroll
        for (int k = 0; k < 4; k++) {
            float flo = __uint_as_float(gr[k] << 16);
            float fhi = __uint_as_float(gr[k] & 0xffff0000u);
            acc[k * 2 + 0] = fmaf(w, flo, acc[k * 2 + 0]);
            acc[k * 2 + 1] = fmaf(w, fhi, acc[k * 2 + 1]);
        }
    }
    #pragma unroll
    for (int k = 0; k < 8; k++) {
        acc[k] += __shfl_xor_sync(0xffffffffu, acc[k], 4);
        acc[k] += __shfl_xor_sync(0xffffffffu, acc[k], 8);
        acc[k] += __shfl_xor_sync(0xffffffffu, acc[k], 16);
    }
    if (sub == 0) {
        float* dst = out + (size_t)n * DIM + h * HD + (lane & 3) * 8;
        float4 w0; w0.x = acc[0]; w0.y = acc[1]; w0.z = acc[2]; w0.w = acc[3];
        float4 w1; w1.x = acc[4]; w1.y = acc[5]; w1.z = acc[6]; w1.w = acc[7];
        *reinterpret_cast<float4*>(dst)     = w0;
        *reinterpret_cast<float4*>(dst + 4) = w1;
    }
}

// ---------------------------------------------------------------------------
// LayerNorm (residual add + LN)
// ---------------------------------------------------------------------------
__global__ void ln_kernel(const float* __restrict__ A, const float* __restrict__ Bb,
                          const float* __restrict__ gamma, const float* __restrict__ beta,
                          float* __restrict__ O) {
    int n = blockIdx.x;
    int c = threadIdx.x;
    float x = A[(size_t)n * DIM + c] + Bb[(size_t)n * DIM + c];
    float s = x, sq = x * x;
    #pragma unroll
    for (int o = 16; o; o >>= 1) {
        s  += __shfl_xor_sync(0xffffffffu, s, o);
        sq += __shfl_xor_sync(0xffffffffu, sq, o);
    }
    __shared__ float sh_s[8], sh_q[8];
    if ((c & 31) == 0) { sh_s[c >> 5] = s; sh_q[c >> 5] = sq; }
    __syncthreads();
    float ts = 0.f, tq = 0.f;
    #pragma unroll
    for (int i = 0; i < 8; i++) { ts += sh_s[i]; tq += sh_q[i]; }
    float mean = ts * (1.0f / (float)DIM);
    float var  = tq * (1.0f / (float)DIM) - mean * mean;
    var = fmaxf(var, 0.f);
    float inv = rsqrtf(var + 1e-5f);
    O[(size_t)n * DIM + c] = (x - mean) * inv * gamma[c] + beta[c];
}

// ---------------------------------------------------------------------------
// Host: tail for one half of the queries on a given stream
// ---------------------------------------------------------------------------
struct TailArgs {
    const float* query; const float* g2; const float* be2;
    const float* g3; const float* be3;
    const float* bo; const float* b1; const float* b2;
    __nv_bfloat16 *Wo_bf, *W1_bf, *W2_bf;
    float *smp, *buf1, *buf2, *xq, *out;
};

static inline void launch_tail_half(const TailArgs& t, int base, cudaStream_t st) {
    const float* q_h   = t.query + (size_t)base * DIM;
    float* smp_h       = t.smp  + (size_t)base * DIM;
    float* buf1_h      = t.buf1 + (size_t)base * DFF;
    float* buf2_h      = t.buf2 + (size_t)base * DIM;
    float* xq_h        = t.xq   + (size_t)base * DIM;
    float* out_h       = t.out  + (size_t)base * DIM;
    mma_gemm64<0><<<dim3(2, NHALF / 64), 256, 0, st>>>(smp_h, t.Wo_bf, t.bo, nullptr, buf2_h, DIM, DIM);
    ln_kernel<<<NHALF, 256, 0, st>>>(q_h, buf2_h, t.g2, t.be2, xq_h);
    mma_gemm64<1><<<dim3(DFF / MBN, NHALF / 64), 256, 0, st>>>(xq_h, t.W1_bf, t.b1, nullptr, buf1_h, DIM, DFF);
    mma_gemm64<0><<<dim3(2, NHALF / 64), 256, 0, st>>>(buf1_h, t.W2_bf, t.b2, nullptr, buf2_h, DFF, DIM);
    ln_kernel<<<NHALF, 256, 0, st>>>(xq_h, buf2_h, t.g3, t.be3, out_h);
}

// ---------------------------------------------------------------------------
// Host orchestration — vproj forked; sample+tail pipelined in query halves.
// ---------------------------------------------------------------------------
extern "C" void kernel_launch(void* const* d_in, const int* in_sizes, int n_in,
                              void* d_out, int out_size) {
    const float* query = (const float*)d_in[0];
    const float* memory = (const float*)d_in[1];
    const float* ref_w  = (const float*)d_in[2];
    const float* Wp1 = (const float*)d_in[5];
    const float* bp1 = (const float*)d_in[6];
    const float* Wp2 = (const float*)d_in[7];
    const float* bp2 = (const float*)d_in[8];
    const float* Wp3 = (const float*)d_in[9];
    const float* bp3 = (const float*)d_in[10];
    const float* Wv  = (const float*)d_in[11];
    const float* bv  = (const float*)d_in[12];
    const float* Wa  = (const float*)d_in[13];
    const float* ba  = (const float*)d_in[14];
    const float* Wb  = (const float*)d_in[15];
    const float* bb  = (const float*)d_in[16];
    const float* Wo  = (const float*)d_in[17];
    const float* bo  = (const float*)d_in[18];
    const float* W1  = (const float*)d_in[19];
    const float* b1  = (const float*)d_in[20];
    const float* W2  = (const float*)d_in[21];
    const float* b2  = (const float*)d_in[22];
    const float* g2  = (const float*)d_in[23];
    const float* be2 = (const float*)d_in[24];
    const float* g3  = (const float*)d_in[25];
    const float* be3 = (const float*)d_in[26];
    float* out = (float*)d_out;

    __nv_bfloat16 *v_bf, *Wv_bf, *Wo_bf, *W1_bf, *W2_bf, *Wp2_bf, *Wp3_bf, *Wab_hi, *Wab_lo;
    float *q, *buf1, *buf2, *smp, *xq, *bab;
    cudaGetSymbolAddress((void**)&v_bf,   g_v_bf);
    cudaGetSymbolAddress((void**)&q,      g_q);
    cudaGetSymbolAddress((void**)&buf1,   g_buf1);
    cudaGetSymbolAddress((void**)&buf2,   g_buf2);
    cudaGetSymbolAddress((void**)&smp,    g_smp);
    cudaGetSymbolAddress((void**)&xq,     g_xq);
    cudaGetSymbolAddress((void**)&Wv_bf,  g_Wv_bf);
    cudaGetSymbolAddress((void**)&Wo_bf,  g_Wo_bf);
    cudaGetSymbolAddress((void**)&W1_bf,  g_W1_bf);
    cudaGetSymbolAddress((void**)&W2_bf,  g_W2_bf);
    cudaGetSymbolAddress((void**)&Wp2_bf, g_Wp2_bf);
    cudaGetSymbolAddress((void**)&Wp3_bf, g_Wp3_bf);
    cudaGetSymbolAddress((void**)&Wab_hi, g_Wab_hi);
    cudaGetSymbolAddress((void**)&Wab_lo, g_Wab_lo);
    cudaGetSymbolAddress((void**)&bab,    g_bab);

    cudaFuncSetAttribute(mma_k256_vproj, cudaFuncAttributeMaxDynamicSharedMemorySize, KSMEM_TOTAL);

    static cudaStream_t s1 = nullptr;
    static cudaEvent_t ev_fork = nullptr, ev_join = nullptr, ev_sa = nullptr, ev_done = nullptr;
    if (s1 == nullptr) {
        cudaStreamCreateWithFlags(&s1, cudaStreamNonBlocking);
        cudaEventCreateWithFlags(&ev_fork, cudaEventDisableTiming);
        cudaEventCreateWithFlags(&ev_join, cudaEventDisableTiming);
        cudaEventCreateWithFlags(&ev_sa,   cudaEventDisableTiming);
        cudaEventCreateWithFlags(&ev_done, cudaEventDisableTiming);
    }

    // (1) Wv conversion — sole gate for vproj
    prep_wv<<<(DIM * DIM + 255) / 256, 256>>>(Wv, Wv_bf);

    // Fork: (2) vproj on side stream
    cudaEventRecord(ev_fork, 0);
    cudaStreamWaitEvent(s1, ev_fork, 0);
    mma_k256_vproj<<<HWSZ / 64, 256, KSMEM_TOTAL, s1>>>(memory, Wv_bf, bv, v_bf);
    cudaEventRecord(ev_join, s1);

    // Main branch (overlaps vproj)
    prep_rest<<<((3 * DIM * DIM + 2 * DFF * DIM) + 255) / 256, 256>>>(
        Wo, Wo_bf, Wp2, Wp2_bf, Wp3, Wp3_bf, W1, W1_bf, W2, W2_bf);
    pack_wab<<<DIM, DIM>>>(Wa, Wb, ba, bb, Wab_hi, Wab_lo, bab);
    sgemm_k8_relu<<<dim3(DIM / BN, NQ / BM), 256>>>(ref_w, Wp1, bp1, buf1, NQ, DIM, 8);
    mma_gemm64<1><<<dim3(2, NQ / 64), 256>>>(buf1, Wp2_bf, bp2, nullptr, buf2, DIM, DIM);
    mma_gemm64<2><<<dim3(2, NQ / 64), 256>>>(buf2, Wp3_bf, bp3, query, q, DIM, DIM);
    mma_gemm64_x3<<<dim3(2, NQ / 64), 256>>>(q, Wab_hi, Wab_lo, bab, buf1, DIM, DIM);

    TailArgs t{query, g2, be2, g3, be3, bo, b1, b2,
               Wo_bf, W1_bf, W2_bf, smp, buf1, buf2, xq, out};

    // Join + pipelined halves:
    //   s0: sampleA -> evSA -> tailA
    //   s1: (wait evSA) sampleB -> tailB  (sampleB overlaps tailA)
    cudaStreamWaitEvent(0, ev_join, 0);
    sample_kernel<<<NHALF, 256>>>(ref_w, buf1, v_bf, smp);
    cudaEventRecord(ev_sa, 0);
    cudaStreamWaitEvent(s1, ev_sa, 0);
    sample_kernel<<<NHALF, 256, 0, s1>>>(
        ref_w + (size_t)NHALF * 8, buf1 + (size_t)NHALF * DIM, v_bf,
        smp + (size_t)NHALF * DIM);
    launch_tail_half(t, 0, 0);
    launch_tail_half(t, NHALF, s1);

    // Join s1 back into the default stream so the graph has a single leaf
    cudaEventRecord(ev_done, s1);
    cudaStreamWaitEvent(0, ev_done, 0);
}

// round 16
// speedup vs baseline: 1.1113x; 1.0700x over previous
#include <cuda_runtime.h>
#include <cuda_bf16.h>
#include <math.h>
#include <cstdint>

// Problem constants
#define NQ   8192
#define DIM  256
#define NH   8
#define HD   32
#define PP   25
#define HH   512
#define WW   512
#define HWSZ (HH * WW)
#define DFF  1024
#define NHALF (NQ / 2)

#define VSCALE 64.0f
#define VISCALE (1.0f / 64.0f)

// ---------------------------------------------------------------------------
// Scratch (device globals)
// ---------------------------------------------------------------------------
__device__ int8_t g_v_i8[(size_t)NH * HWSZ * HD];   // head-major int8 v (64MB, L2-resident)
__device__ float g_q[NQ * DIM];
__device__ float g_buf1[NQ * DFF];
__device__ float g_buf2[NQ * DIM];
__device__ float g_smp[NQ * DIM];
__device__ float g_xq[NQ * DIM];
__device__ __nv_bfloat16 g_Wv_bf[DIM * DIM];
__device__ __nv_bfloat16 g_Wo_bf[DIM * DIM];
__device__ __nv_bfloat16 g_W1_bf[DFF * DIM];
__device__ __nv_bfloat16 g_W2_bf[DIM * DFF];
__device__ __nv_bfloat16 g_Wp2_bf[DIM * DIM];
__device__ __nv_bfloat16 g_Wp3_bf[DIM * DIM];
__device__ __nv_bfloat16 g_Wab_hi[DIM * DIM];
__device__ __nv_bfloat16 g_Wab_lo[DIM * DIM];
__device__ float g_bab[DIM];

__device__ __forceinline__ uint32_t smem_to_u32(const void* p) {
    uint32_t a;
    asm("{ .reg .u64 t; cvta.to.shared.u64 t, %1; cvt.u32.u64 %0, t; }" : "=r"(a) : "l"(p));
    return a;
}
#define CP_ASYNC16(dst, src) \
    asm volatile("cp.async.cg.shared.global [%0], [%1], 16;" :: "r"(dst), "l"(src))
#define CP_COMMIT() asm volatile("cp.async.commit_group;" ::: "memory")
#define CP_WAIT0()  asm volatile("cp.async.wait_group 0;" ::: "memory")

#define MBM 128
#define MBN 128
#define MBK 32
#define MSTR 40   // smem row stride: 20 words, 20 % 8 == 4 -> conflict-free ldmatrix

// ---------------------------------------------------------------------------
// 64x128-tile warp-MMA bf16 GEMM — high-occupancy variant.
// EPI: 0=+bias, 1=+bias+relu, 2=+bias+Res
// ---------------------------------------------------------------------------
template <int EPI>
__global__ void __launch_bounds__(256, 3)
mma_gemm64(const float* __restrict__ A, const __nv_bfloat16* __restrict__ B,
           const float* __restrict__ bias, const float* __restrict__ Res,
           float* __restrict__ C, int K, int N) {
    __shared__ __nv_bfloat16 As[64 * MSTR];
    __shared__ __nv_bfloat16 Bs[MBN * MSTR];
    const uint32_t as_base = smem_to_u32(As);
    const uint32_t bs_base = smem_to_u32(Bs);

    const int tid  = threadIdx.x;
    const int wid  = tid >> 5;
    const int lane = tid & 31;
    const int warp_m = wid >> 2;
    const int warp_n = wid & 3;
    const int m0 = blockIdx.y * 64;
    const int n0 = blockIdx.x * MBN;

    float acc[2][4][4];
    #pragma unroll
    for (int i = 0; i < 2; i++)
        #pragma unroll
        for (int j = 0; j < 4; j++)
            #pragma unroll
            for (int r = 0; r < 4; r++) acc[i][j][r] = 0.f;

    const int l16 = lane & 15;
    const uint32_t a_lm_off = (uint32_t)((warp_m * 32 + l16) * MSTR + (lane >> 4) * 8) * 2;
    const uint32_t b_lm_off = (uint32_t)((warp_n * 32 + (l16 & 7)) * MSTR + ((l16 >> 3) * 8)) * 2;

    for (int k0 = 0; k0 < K; k0 += MBK) {
        #pragma unroll
        for (int i = 0; i < 2; i++) {
            int e = i * 256 + tid;
            int r = e >> 3;
            int c = (e & 7) << 2;
            float4 av = *reinterpret_cast<const float4*>(A + (size_t)(m0 + r) * K + k0 + c);
            uint32_t p0, p1;
            asm("cvt.rn.satfinite.bf16x2.f32 %0, %1, %2;" : "=r"(p0) : "f"(av.y), "f"(av.x));
            asm("cvt.rn.satfinite.bf16x2.f32 %0, %1, %2;" : "=r"(p1) : "f"(av.w), "f"(av.z));
            uint32_t addr = as_base + (uint32_t)(r * MSTR + c) * 2;
            asm volatile("st.shared.v2.b32 [%0], {%1, %2};" :: "r"(addr), "r"(p0), "r"(p1));
        }
        #pragma unroll
        for (int i = 0; i < 2; i++) {
            int e = i * 256 + tid;
            int r = e >> 2;
            int c = (e & 3) << 3;
            uint4 bv = *reinterpret_cast<const uint4*>(B + (size_t)(n0 + r) * K + k0 + c);
            uint32_t addr = bs_base + (uint32_t)(r * MSTR + c) * 2;
            asm volatile("st.shared.v4.b32 [%0], {%1, %2, %3, %4};"
                :: "r"(addr), "r"(bv.x), "r"(bv.y), "r"(bv.z), "r"(bv.w));
        }
        __syncthreads();

        #pragma unroll
        for (int ks = 0; ks < 2; ks++) {
            uint32_t af[2][4];
            #pragma unroll
            for (int mt = 0; mt < 2; mt++) {
                uint32_t addr = as_base + a_lm_off + (uint32_t)(mt * 16 * MSTR + ks * 16) * 2;
                asm volatile("ldmatrix.sync.aligned.m8n8.x4.shared.b16 {%0,%1,%2,%3}, [%4];"
                    : "=r"(af[mt][0]), "=r"(af[mt][1]), "=r"(af[mt][2]), "=r"(af[mt][3])
                    : "r"(addr));
            }
            uint32_t bf[4][2];
            #pragma unroll
            for (int nt = 0; nt < 4; nt++) {
                uint32_t addr = bs_base + b_lm_off + (uint32_t)(nt * 8 * MSTR + ks * 16) * 2;
                asm volatile("ldmatrix.sync.aligned.m8n8.x2.shared.b16 {%0,%1}, [%2];"
                    : "=r"(bf[nt][0]), "=r"(bf[nt][1]) : "r"(addr));
            }
            #pragma unroll
            for (int mt = 0; mt < 2; mt++)
                #pragma unroll
                for (int nt = 0; nt < 4; nt++) {
                    asm volatile(
                        "mma.sync.aligned.m16n8k16.row.col.f32.bf16.bf16.f32 "
                        "{%0,%1,%2,%3}, {%4,%5,%6,%7}, {%8,%9}, {%0,%1,%2,%3};"
                        : "+f"(acc[mt][nt][0]), "+f"(acc[mt][nt][1]),
                          "+f"(acc[mt][nt][2]), "+f"(acc[mt][nt][3])
                        : "r"(af[mt][0]), "r"(af[mt][1]), "r"(af[mt][2]), "r"(af[mt][3]),
                          "r"(bf[nt][0]), "r"(bf[nt][1]));
                }
        }
        __syncthreads();
    }

    const int row_in = lane >> 2;
    const int col_in = (lane & 3) << 1;
    #pragma unroll
    for (int mt = 0; mt < 2; mt++) {
        #pragma unroll
        for (int nt = 0; nt < 4; nt++) {
            int n = n0 + warp_n * 32 + nt * 8 + col_in;
            float b0 = bias[n], b1 = bias[n + 1];
            #pragma unroll
            for (int half = 0; half < 2; half++) {
                int m = m0 + warp_m * 32 + mt * 16 + row_in + half * 8;
                float2 o;
                o.x = acc[mt][nt][half * 2 + 0] + b0;
                o.y = acc[mt][nt][half * 2 + 1] + b1;
                if (EPI == 1) { o.x = fmaxf(o.x, 0.f); o.y = fmaxf(o.y, 0.f); }
                if (EPI == 2) {
                    float2 rr = *reinterpret_cast<const float2*>(Res + (size_t)m * N + n);
                    o.x += rr.x; o.y += rr.y;
                }
                *reinterpret_cast<float2*>(C + (size_t)m * N + n) = o;
            }
        }
    }
}

// ---------------------------------------------------------------------------
// 64x128-tile bf16x3 split-precision GEMM (near-fp32) — attn-logits + offsets.
// ---------------------------------------------------------------------------
__global__ void __launch_bounds__(256, 3)
mma_gemm64_x3(const float* __restrict__ A, const __nv_bfloat16* __restrict__ Bhi,
              const __nv_bfloat16* __restrict__ Blo, const float* __restrict__ bias,
              float* __restrict__ C, int K, int N) {
    __shared__ __nv_bfloat16 AsH[64 * MSTR];
    __shared__ __nv_bfloat16 AsL[64 * MSTR];
    __shared__ __nv_bfloat16 BsH[MBN * MSTR];
    __shared__ __nv_bfloat16 BsL[MBN * MSTR];
    const uint32_t ash = smem_to_u32(AsH);
    const uint32_t asl = smem_to_u32(AsL);
    const uint32_t bsh = smem_to_u32(BsH);
    const uint32_t bsl = smem_to_u32(BsL);

    const int tid  = threadIdx.x;
    const int wid  = tid >> 5;
    const int lane = tid & 31;
    const int warp_m = wid >> 2;
    const int warp_n = wid & 3;
    const int m0 = blockIdx.y * 64;
    const int n0 = blockIdx.x * MBN;

    float acc[2][4][4];
    #pragma unroll
    for (int i = 0; i < 2; i++)
        #pragma unroll
        for (int j = 0; j < 4; j++)
            #pragma unroll
            for (int r = 0; r < 4; r++) acc[i][j][r] = 0.f;

    const int l16 = lane & 15;
    const uint32_t a_lm_off = (uint32_t)((warp_m * 32 + l16) * MSTR + (lane >> 4) * 8) * 2;
    const uint32_t b_lm_off = (uint32_t)((warp_n * 32 + (l16 & 7)) * MSTR + ((l16 >> 3) * 8)) * 2;

    for (int k0 = 0; k0 < K; k0 += MBK) {
        #pragma unroll
        for (int i = 0; i < 2; i++) {
            int e = i * 256 + tid;
            int r = e >> 3;
            int c = (e & 7) << 2;
            float4 av = *reinterpret_cast<const float4*>(A + (size_t)(m0 + r) * K + k0 + c);
            __nv_bfloat16 hx = __float2bfloat16(av.x);
            __nv_bfloat16 hy = __float2bfloat16(av.y);
            __nv_bfloat16 hz = __float2bfloat16(av.z);
            __nv_bfloat16 hw = __float2bfloat16(av.w);
            __nv_bfloat162 h01; h01.x = hx; h01.y = hy;
            __nv_bfloat162 h23; h23.x = hz; h23.y = hw;
            uint32_t hp0 = *reinterpret_cast<uint32_t*>(&h01);
            uint32_t hp1 = *reinterpret_cast<uint32_t*>(&h23);
            float lx = av.x - __bfloat162float(hx);
            float ly = av.y - __bfloat162float(hy);
            float lz = av.z - __bfloat162float(hz);
            float lw = av.w - __bfloat162float(hw);
            uint32_t lp0, lp1;
            asm("cvt.rn.satfinite.bf16x2.f32 %0, %1, %2;" : "=r"(lp0) : "f"(ly), "f"(lx));
            asm("cvt.rn.satfinite.bf16x2.f32 %0, %1, %2;" : "=r"(lp1) : "f"(lw), "f"(lz));
            uint32_t off = (uint32_t)(r * MSTR + c) * 2;
            asm volatile("st.shared.v2.b32 [%0], {%1, %2};" :: "r"(ash + off), "r"(hp0), "r"(hp1));
            asm volatile("st.shared.v2.b32 [%0], {%1, %2};" :: "r"(asl + off), "r"(lp0), "r"(lp1));
        }
        #pragma unroll
        for (int i = 0; i < 2; i++) {
            int e = i * 256 + tid;
            int r = e >> 2;
            int c = (e & 3) << 3;
            uint4 bh = *reinterpret_cast<const uint4*>(Bhi + (size_t)(n0 + r) * K + k0 + c);
            uint4 bl = *reinterpret_cast<const uint4*>(Blo + (size_t)(n0 + r) * K + k0 + c);
            uint32_t off = (uint32_t)(r * MSTR + c) * 2;
            asm volatile("st.shared.v4.b32 [%0], {%1, %2, %3, %4};"
                :: "r"(bsh + off), "r"(bh.x), "r"(bh.y), "r"(bh.z), "r"(bh.w));
            asm volatile("st.shared.v4.b32 [%0], {%1, %2, %3, %4};"
                :: "r"(bsl + off), "r"(bl.x), "r"(bl.y), "r"(bl.z), "r"(bl.w));
        }
        __syncthreads();

        #pragma unroll
        for (int pass = 0; pass < 3; pass++) {
            uint32_t abase = (pass == 2) ? asl : ash;
            uint32_t bbase = (pass == 1) ? bsl : bsh;
            #pragma unroll
            for (int ks = 0; ks < 2; ks++) {
                uint32_t af[2][4];
                #pragma unroll
                for (int mt = 0; mt < 2; mt++) {
                    uint32_t addr = abase + a_lm_off + (uint32_t)(mt * 16 * MSTR + ks * 16) * 2;
                    asm volatile("ldmatrix.sync.aligned.m8n8.x4.shared.b16 {%0,%1,%2,%3}, [%4];"
                        : "=r"(af[mt][0]), "=r"(af[mt][1]), "=r"(af[mt][2]), "=r"(af[mt][3])
                        : "r"(addr));
                }
                uint32_t bf[4][2];
                #pragma unroll
                for (int nt = 0; nt < 4; nt++) {
                    uint32_t addr = bbase + b_lm_off + (uint32_t)(nt * 8 * MSTR + ks * 16) * 2;
                    asm volatile("ldmatrix.sync.aligned.m8n8.x2.shared.b16 {%0,%1}, [%2];"
                        : "=r"(bf[nt][0]), "=r"(bf[nt][1]) : "r"(addr));
                }
                #pragma unroll
                for (int mt = 0; mt < 2; mt++)
                    #pragma unroll
                    for (int nt = 0; nt < 4; nt++) {
                        asm volatile(
                            "mma.sync.aligned.m16n8k16.row.col.f32.bf16.bf16.f32 "
                            "{%0,%1,%2,%3}, {%4,%5,%6,%7}, {%8,%9}, {%0,%1,%2,%3};"
                            : "+f"(acc[mt][nt][0]), "+f"(acc[mt][nt][1]),
                              "+f"(acc[mt][nt][2]), "+f"(acc[mt][nt][3])
                            : "r"(af[mt][0]), "r"(af[mt][1]), "r"(af[mt][2]), "r"(af[mt][3]),
                              "r"(bf[nt][0]), "r"(bf[nt][1]));
                    }
            }
        }
        __syncthreads();
    }

    const int row_in = lane >> 2;
    const int col_in = (lane & 3) << 1;
    #pragma unroll
    for (int mt = 0; mt < 2; mt++) {
        #pragma unroll
        for (int nt = 0; nt < 4; nt++) {
            int n = n0 + warp_n * 32 + nt * 8 + col_in;
            float b0 = bias[n], b1 = bias[n + 1];
            #pragma unroll
            for (int half = 0; half < 2; half++) {
                int m = m0 + warp_m * 32 + mt * 16 + row_in + half * 8;
                float2 o;
                o.x = acc[mt][nt][half * 2 + 0] + b0;
                o.y = acc[mt][nt][half * 2 + 1] + b1;
                *reinterpret_cast<float2*>(C + (size_t)m * N + n) = o;
            }
        }
    }
}

// ---------------------------------------------------------------------------
// A-resident K=256 v-projection, M=64 per CTA, cp.async B pipeline.
// Output head-major INT8 (scale 64): v[h][HW][32].  3 CTAs/SM.
// ---------------------------------------------------------------------------
#define ASTRIDE 264
#define K256 256
#define VB_BUF (128 * MSTR)
#define KSMEM_TOTAL (64 * ASTRIDE * 2 + 2 * VB_BUF * 2)

__global__ void __launch_bounds__(256, 3)
mma_k256_vproj(const float* __restrict__ A, const __nv_bfloat16* __restrict__ B,
               const float* __restrict__ bias, int8_t* __restrict__ VT) {
    extern __shared__ __nv_bfloat16 sm[];
    __nv_bfloat16* As = sm;
    __nv_bfloat16* Bs = sm + 64 * ASTRIDE;
    const uint32_t as_base = smem_to_u32(As);
    const uint32_t bs_base = smem_to_u32(Bs);

    const int tid  = threadIdx.x;
    const int wid  = tid >> 5;
    const int lane = tid & 31;
    const int warp_m = wid >> 2;
    const int warp_n = wid & 3;
    const int m0 = blockIdx.x * 64;

    #pragma unroll
    for (int i = 0; i < 16; i++) {
        int e = i * 256 + tid;
        int r = e >> 6;
        int c = (e & 63) << 2;
        float4 av = *reinterpret_cast<const float4*>(A + (size_t)(m0 + r) * K256 + c);
        uint32_t p0, p1;
        asm("cvt.rn.satfinite.bf16x2.f32 %0, %1, %2;" : "=r"(p0) : "f"(av.y), "f"(av.x));
        asm("cvt.rn.satfinite.bf16x2.f32 %0, %1, %2;" : "=r"(p1) : "f"(av.w), "f"(av.z));
        uint32_t addr = as_base + (uint32_t)(r * ASTRIDE + c) * 2;
        asm volatile("st.shared.v2.b32 [%0], {%1, %2};" :: "r"(addr), "r"(p0), "r"(p1));
    }

    const int l16 = lane & 15;
    const uint32_t a_lm_off = (uint32_t)((warp_m * 32 + l16) * ASTRIDE + (lane >> 4) * 8) * 2;
    const uint32_t b_lm_off = (uint32_t)((warp_n * 32 + (l16 & 7)) * MSTR + ((l16 >> 3) * 8)) * 2;
    const int row_in = lane >> 2;
    const int col_in = (lane & 3) << 1;

    for (int nh = 0; nh < 2; nh++) {
        const int n0 = nh * 128;
        float acc[2][4][4];
        #pragma unroll
        for (int i = 0; i < 2; i++)
            #pragma unroll
            for (int j = 0; j < 4; j++)
                #pragma unroll
                for (int r = 0; r < 4; r++) acc[i][j][r] = 0.f;

        #pragma unroll
        for (int i = 0; i < 2; i++) {
            int e = i * 256 + tid;
            int r = e >> 2;
            int c = (e & 3) << 3;
            uint32_t dst = bs_base + (uint32_t)(r * MSTR + c) * 2;
            const __nv_bfloat16* src = B + (size_t)(n0 + r) * K256 + c;
            CP_ASYNC16(dst, src);
        }
        CP_COMMIT();
        CP_WAIT0();
        __syncthreads();

        for (int ks8 = 0; ks8 < 8; ks8++) {
            int cur = ks8 & 1;
            if (ks8 < 7) {
                uint32_t dbuf = bs_base + (uint32_t)((cur ^ 1) * VB_BUF) * 2;
                #pragma unroll
                for (int i = 0; i < 2; i++) {
                    int e = i * 256 + tid;
                    int r = e >> 2;
                    int c = (e & 3) << 3;
                    uint32_t dst = dbuf + (uint32_t)(r * MSTR + c) * 2;
                    const __nv_bfloat16* src = B + (size_t)(n0 + r) * K256 + (ks8 + 1) * 32 + c;
                    CP_ASYNC16(dst, src);
                }
                CP_COMMIT();
            }
            uint32_t cbuf = bs_base + (uint32_t)(cur * VB_BUF) * 2;
            #pragma unroll
            for (int sub = 0; sub < 2; sub++) {
                int kk = ks8 * 32 + sub * 16;
                uint32_t af[2][4];
                #pragma unroll
                for (int mt = 0; mt < 2; mt++) {
                    uint32_t addr = as_base + a_lm_off + (uint32_t)(mt * 16 * ASTRIDE + kk) * 2;
                    asm volatile("ldmatrix.sync.aligned.m8n8.x4.shared.b16 {%0,%1,%2,%3}, [%4];"
                        : "=r"(af[mt][0]), "=r"(af[mt][1]), "=r"(af[mt][2]), "=r"(af[mt][3])
                        : "r"(addr));
                }
                uint32_t bf[4][2];
                #pragma unroll
                for (int nt = 0; nt < 4; nt++) {
                    uint32_t addr = cbuf + b_lm_off + (uint32_t)(nt * 8 * MSTR + sub * 16) * 2;
                    asm volatile("ldmatrix.sync.aligned.m8n8.x2.shared.b16 {%0,%1}, [%2];"
                        : "=r"(bf[nt][0]), "=r"(bf[nt][1]) : "r"(addr));
                }
                #pragma unroll
                for (int mt = 0; mt < 2; mt++)
                    #pragma unroll
                    for (int nt = 0; nt < 4; nt++) {
                        asm volatile(
                            "mma.sync.aligned.m16n8k16.row.col.f32.bf16.bf16.f32 "
                            "{%0,%1,%2,%3}, {%4,%5,%6,%7}, {%8,%9}, {%0,%1,%2,%3};"
                            : "+f"(acc[mt][nt][0]), "+f"(acc[mt][nt][1]),
                              "+f"(acc[mt][nt][2]), "+f"(acc[mt][nt][3])
                            : "r"(af[mt][0]), "r"(af[mt][1]), "r"(af[mt][2]), "r"(af[mt][3]),
                              "r"(bf[nt][0]), "r"(bf[nt][1]));
                    }
            }
            if (ks8 < 7) { CP_WAIT0(); }
            __syncthreads();
        }

        const int head = nh * 4 + warp_n;
        int8_t* vh = VT + (size_t)head * HWSZ * HD;
        #pragma unroll
        for (int mt = 0; mt < 2; mt++) {
            #pragma unroll
            for (int nt = 0; nt < 4; nt++) {
                int ch = nt * 8 + col_in;
                int n = n0 + warp_n * 32 + ch;
                float b0 = bias[n], b1 = bias[n + 1];
                #pragma unroll
                for (int half = 0; half < 2; half++) {
                    int m = m0 + warp_m * 32 + mt * 16 + row_in + half * 8;
                    float ox = (acc[mt][nt][half * 2 + 0] + b0) * VSCALE;
                    float oy = (acc[mt][nt][half * 2 + 1] + b1) * VSCALE;
                    int qx = max(min(__float2int_rn(ox),  127), -127);
                    int qy = max(min(__float2int_rn(oy),  127), -127);
                    uint16_t pk = (uint16_t)((qx & 0xff) | ((qy & 0xff) << 8));
                    *reinterpret_cast<uint16_t*>(vh + (size_t)m * HD + ch) = pk;
                }
            }
        }
        __syncthreads();
    }
}

// ---------------------------------------------------------------------------
// Weight prep
// ---------------------------------------------------------------------------
__global__ void prep_wv(const float* __restrict__ Wv, __nv_bfloat16* __restrict__ dWv) {
    int i = blockIdx.x * 256 + threadIdx.x;
    if (i < DIM * DIM) dWv[i] = __float2bfloat16(Wv[i]);
}

__global__ void prep_rest(const float* __restrict__ Wo,  __nv_bfloat16* __restrict__ dWo,
                          const float* __restrict__ Wp2, __nv_bfloat16* __restrict__ dWp2,
                          const float* __restrict__ Wp3, __nv_bfloat16* __restrict__ dWp3,
                          const float* __restrict__ W1,  __nv_bfloat16* __restrict__ dW1,
                          const float* __restrict__ W2,  __nv_bfloat16* __restrict__ dW2) {
    int i = blockIdx.x * 256 + threadIdx.x;
    const int S = DIM * DIM;
    const int L = DFF * DIM;
    if (i < S)                    dWo[i] = __float2bfloat16(Wo[i]);
    else if (i < 2 * S)           dWp2[i - S] = __float2bfloat16(Wp2[i - S]);
    else if (i < 3 * S)           dWp3[i - 2 * S] = __float2bfloat16(Wp3[i - 2 * S]);
    else if (i < 3 * S + L)       dW1[i - 3 * S] = __float2bfloat16(W1[i - 3 * S]);
    else if (i < 3 * S + 2 * L)   dW2[i - 3 * S - L] = __float2bfloat16(W2[i - 3 * S - L]);
}

__global__ void pack_wab(const float* __restrict__ Wa, const float* __restrict__ Wb,
                         const float* __restrict__ ba, const float* __restrict__ bb,
                         __nv_bfloat16* __restrict__ Whi, __nv_bfloat16* __restrict__ Wlo,
                         float* __restrict__ bab) {
    int row = blockIdx.x;
    int col = threadIdx.x;
    float w = 0.f;
    if (row < 200)      w = Wa[row * DIM + col];
    else if (row < 240) w = Wb[(row - 200) * DIM + col];
    __nv_bfloat16 hi = __float2bfloat16(w);
    Whi[row * DIM + col] = hi;
    Wlo[row * DIM + col] = __float2bfloat16(w - __bfloat162float(hi));
    if (col == 0) {
        float b = 0.f;
        if (row < 200)      b = ba[row];
        else if (row < 240) b = bb[row - 200];
        bab[row] = b;
    }
}

// ---------------------------------------------------------------------------
// fp32 SGEMM (tiny K=8 first pos-MLP layer)
// ---------------------------------------------------------------------------
#define BM 64
#define BN 64
#define BKT 16

__global__ void sgemm_k8_relu(const float* __restrict__ A, const float* __restrict__ B,
                              const float* __restrict__ bias, float* __restrict__ C,
                              int M, int N, int K) {
    __shared__ float As[BKT][BM];
    __shared__ float Bs[BKT][BN];
    const int tid  = threadIdx.x;
    const int brow = blockIdx.y * BM;
    const int bcol = blockIdx.x * BN;
    const int tx = tid & 15;
    const int ty = tid >> 4;
    const int lr = tid >> 2;
    const int lk = (tid & 3) << 2;

    float acc[4][4] = {};
    for (int k0 = 0; k0 < K; k0 += BKT) {
        #pragma unroll
        for (int i = 0; i < 4; i++) {
            int k = k0 + lk + i;
            As[lk + i][lr] = (k < K) ? A[(size_t)(brow + lr) * K + k] : 0.f;
            Bs[lk + i][lr] = (k < K) ? B[(size_t)(bcol + lr) * K + k] : 0.f;
        }
        __syncthreads();
        #pragma unroll
        for (int kk = 0; kk < BKT; kk++) {
            float4 a4 = *reinterpret_cast<const float4*>(&As[kk][ty << 2]);
            float4 b4 = *reinterpret_cast<const float4*>(&Bs[kk][tx << 2]);
            float ar[4] = {a4.x, a4.y, a4.z, a4.w};
            float br[4] = {b4.x, b4.y, b4.z, b4.w};
            #pragma unroll
            for (int i = 0; i < 4; i++)
                #pragma unroll
                for (int j = 0; j < 4; j++)
                    acc[i][j] = fmaf(ar[i], br[j], acc[i][j]);
        }
        __syncthreads();
    }
    #pragma unroll
    for (int i = 0; i < 4; i++) {
        int r = brow + (ty << 2) + i;
        #pragma unroll
        for (int j = 0; j < 4; j++) {
            int c = bcol + (tx << 2) + j;
            C[(size_t)r * N + c] = fmaxf(acc[i][j] + bias[c], 0.f);
        }
    }
}

// ---------------------------------------------------------------------------
// Deformable bilinear sampling v5 — v4 gather structure on int8 L2-resident v.
// Phase 1: lanes 0-24 emit 4 (byte-offset, premultiplied weight) records.
// Phase 2: 13 rounds; lane handles octet (lane&3) of record (r*8 + lane>>2):
//          LDS.64 + LDG.64 (8 int8) + byte-unpack + 8 FMA.
// Reduce: shfl-xor 4/8/16; lanes 0-3 write 8 floats (scaled by 1/64).
// ---------------------------------------------------------------------------
__global__ void sample_kernel(const float* __restrict__ rw,
                              const float* __restrict__ ao,
                              const int8_t* __restrict__ v,
                              float* __restrict__ out) {
    __shared__ float2 s_aw[NH][104];

    int n    = blockIdx.x;
    int h    = threadIdx.x >> 5;
    int lane = threadIdx.x & 31;

    const float* aon = ao + (size_t)n * DIM;
    float logit = (lane < PP) ? aon[h * PP + lane] : -1e30f;
    float mx = logit;
    #pragma unroll
    for (int o = 16; o; o >>= 1) mx = fmaxf(mx, __shfl_xor_sync(0xffffffffu, mx, o));
    float e = (lane < PP) ? expf(logit - mx) : 0.f;
    float s = e;
    #pragma unroll
    for (int o = 16; o; o >>= 1) s += __shfl_xor_sync(0xffffffffu, s, o);
    float myattn = e / s;

    const float* rwn = rw + (size_t)n * 8;
    float rw0 = rwn[0], rw1 = rwn[1], rw3 = rwn[3], rw4 = rwn[4], rw6 = rwn[6];
    const float* offn = aon + 200 + h * 5;
    float o0 = offn[0], o1 = offn[1], o2 = offn[2], o3 = offn[3], o4 = offn[4];

    float cx = rw0 + o0 * 0.125f * rw3;
    float cy = rw1 + o1 * 0.125f * rw4;
    float sx = fmaxf(rw3 + o2 * 0.125f * rw3, 0.f);
    float sy = fmaxf(rw4 + o3 * 0.125f * rw4, 0.f);
    float ang = (rw6 + o4 * (1.0f / 16.0f)) * 6.2831853071795864769f;
    float sth, cth;
    __sincosf(ang, &sth, &cth);

    if (lane < PP) {
        int a = lane / 5, b = lane % 5;
        float gx = sx * (float)(b - 2) * 0.2f;
        float gy = sy * (float)(a - 2) * 0.2f;
        float lx = cx + gx * cth - gy * sth;
        float ly = cy + gx * sth + gy * cth;
        float x = lx * (float)WW - 0.5f;
        float y = ly * (float)HH - 0.5f;
        float x0f = floorf(x), y0f = floorf(y);
        float fx = x - x0f, fy = y - y0f;
        int x0 = (int)x0f, y0 = (int)y0f;
        bool vx0 = (x0 >= 0) && (x0 <= WW - 1);
        bool vx1 = (x0 + 1 >= 0) && (x0 + 1 <= WW - 1);
        bool vy0 = (y0 >= 0) && (y0 <= HH - 1);
        bool vy1 = (y0 + 1 >= 0) && (y0 + 1 <= HH - 1);
        int xc0 = min(max(x0, 0), WW - 1);
        int xc1 = min(max(x0 + 1, 0), WW - 1);
        int yc0 = min(max(y0, 0), HH - 1);
        int yc1 = min(max(y0 + 1, 0), HH - 1);
        float wx0 = 1.f - fx, wx1 = fx;
        float wy0 = 1.f - fy, wy1 = fy;
        float ap = myattn;
        int p4 = lane * 4;
        s_aw[h][p4 + 0] = make_float2(
            __int_as_float((yc0 * WW + xc0) * HD),
            (vx0 && vy0) ? (ap * wx0) * wy0 : 0.f);
        s_aw[h][p4 + 1] = make_float2(
            __int_as_float((yc1 * WW + xc0) * HD),
            (vx0 && vy1) ? (ap * wx0) * wy1 : 0.f);
        s_aw[h][p4 + 2] = make_float2(
            __int_as_float((yc0 * WW + xc1) * HD),
            (vx1 && vy0) ? (ap * wx1) * wy0 : 0.f);
        s_aw[h][p4 + 3] = make_float2(
            __int_as_float((yc1 * WW + xc1) * HD),
            (vx1 && vy1) ? (ap * wx1) * wy1 : 0.f);
    } else if (lane < PP + 4) {
        s_aw[h][100 + (lane - PP)] = make_float2(__int_as_float(0), 0.f);
    }
    __syncwarp();

    const char* vb = reinterpret_cast<const char*>(v + (size_t)h * HWSZ * HD);
    const int oct8 = (lane & 3) * 8;
    const int sub  = lane >> 2;
    float acc[8];
    #pragma unroll
    for (int k = 0; k < 8; k++) acc[k] = 0.f;

    #pragma unroll
    for (int r = 0; r < 13; r++) {
        float2 aw = s_aw[h][r * 8 + sub];
        float w = aw.y;
        const uint2* ptr = reinterpret_cast<const uint2*>(
            vb + (size_t)(uint32_t)__float_as_int(aw.x) + oct8);
        uint2 g = *ptr;
        uint32_t gr[2] = {g.x, g.y};
        #pragma unroll
        for (int j = 0; j < 2; j++) {
            uint32_t gw = gr[j];
            #pragma unroll
            for (int k = 0; k < 4; k++) {
                int q = (int)((int8_t)(gw >> (8 * k)));
                acc[j * 4 + k] = fmaf(w, (float)q, acc[j * 4 + k]);
            }
        }
    }
    #pragma unroll
    for (int k = 0; k < 8; k++) {
        acc[k] += __shfl_xor_sync(0xffffffffu, acc[k], 4);
        acc[k] += __shfl_xor_sync(0xffffffffu, acc[k], 8);
        acc[k] += __shfl_xor_sync(0xffffffffu, acc[k], 16);
    }
    if (sub == 0) {
        float* dst = out + (size_t)n * DIM + h * HD + (lane & 3) * 8;
        float4 w0; w0.x = acc[0] * VISCALE; w0.y = acc[1] * VISCALE;
        w0.z = acc[2] * VISCALE; w0.w = acc[3] * VISCALE;
        float4 w1; w1.x = acc[4] * VISCALE; w1.y = acc[5] * VISCALE;
        w1.z = acc[6] * VISCALE; w1.w = acc[7] * VISCALE;
        *reinterpret_cast<float4*>(dst)     = w0;
        *reinterpret_cast<float4*>(dst + 4) = w1;
    }
}

// ---------------------------------------------------------------------------
// LayerNorm (residual add + LN)
// ---------------------------------------------------------------------------
__global__ void ln_kernel(const float* __restrict__ A, const float* __restrict__ Bb,
                          const float* __restrict__ gamma, const float* __restrict__ beta,
                          float* __restrict__ O) {
    int n = blockIdx.x;
    int c = threadIdx.x;
    float x = A[(size_t)n * DIM + c] + Bb[(size_t)n * DIM + c];
    float s = x, sq = x * x;
    #pragma unroll
    for (int o = 16; o; o >>= 1) {
        s  += __shfl_xor_sync(0xffffffffu, s, o);
        sq += __shfl_xor_sync(0xffffffffu, sq, o);
    }
    __shared__ float sh_s[8], sh_q[8];
    if ((c & 31) == 0) { sh_s[c >> 5] = s; sh_q[c >> 5] = sq; }
    __syncthreads();
    float ts = 0.f, tq = 0.f;
    #pragma unroll
    for (int i = 0; i < 8; i++) { ts += sh_s[i]; tq += sh_q[i]; }
    float mean = ts * (1.0f / (float)DIM);
    float var  = tq * (1.0f / (float)DIM) - mean * mean;
    var = fmaxf(var, 0.f);
    float inv = rsqrtf(var + 1e-5f);
    O[(size_t)n * DIM + c] = (x - mean) * inv * gamma[c] + beta[c];
}

// ---------------------------------------------------------------------------
// Host: tail for one half of the queries on a given stream
// ---------------------------------------------------------------------------
struct TailArgs {
    const float* query; const float* g2; const float* be2;
    const float* g3; const float* be3;
    const float* bo; const float* b1; const float* b2;
    __nv_bfloat16 *Wo_bf, *W1_bf, *W2_bf;
    float *smp, *buf1, *buf2, *xq, *out;
};

static inline void launch_tail_half(const TailArgs& t, int base, cudaStream_t st) {
    const float* q_h   = t.query + (size_t)base * DIM;
    float* smp_h       = t.smp  + (size_t)base * DIM;
    float* buf1_h      = t.buf1 + (size_t)base * DFF;
    float* buf2_h      = t.buf2 + (size_t)base * DIM;
    float* xq_h        = t.xq   + (size_t)base * DIM;
    float* out_h       = t.out  + (size_t)base * DIM;
    mma_gemm64<0><<<dim3(2, NHALF / 64), 256, 0, st>>>(smp_h, t.Wo_bf, t.bo, nullptr, buf2_h, DIM, DIM);
    ln_kernel<<<NHALF, 256, 0, st>>>(q_h, buf2_h, t.g2, t.be2, xq_h);
    mma_gemm64<1><<<dim3(DFF / MBN, NHALF / 64), 256, 0, st>>>(xq_h, t.W1_bf, t.b1, nullptr, buf1_h, DIM, DFF);
    mma_gemm64<0><<<dim3(2, NHALF / 64), 256, 0, st>>>(buf1_h, t.W2_bf, t.b2, nullptr, buf2_h, DFF, DIM);
    ln_kernel<<<NHALF, 256, 0, st>>>(xq_h, buf2_h, t.g3, t.be3, out_h);
}

// ---------------------------------------------------------------------------
// Host orchestration — vproj forked; sample+tail pipelined in query halves.
// ---------------------------------------------------------------------------
extern "C" void kernel_launch(void* const* d_in, const int* in_sizes, int n_in,
                              void* d_out, int out_size) {
    const float* query = (const float*)d_in[0];
    const float* memory = (const float*)d_in[1];
    const float* ref_w  = (const float*)d_in[2];
    const float* Wp1 = (const float*)d_in[5];
    const float* bp1 = (const float*)d_in[6];
    const float* Wp2 = (const float*)d_in[7];
    const float* bp2 = (const float*)d_in[8];
    const float* Wp3 = (const float*)d_in[9];
    const float* bp3 = (const float*)d_in[10];
    const float* Wv  = (const float*)d_in[11];
    const float* bv  = (const float*)d_in[12];
    const float* Wa  = (const float*)d_in[13];
    const float* ba  = (const float*)d_in[14];
    const float* Wb  = (const float*)d_in[15];
    const float* bb  = (const float*)d_in[16];
    const float* Wo  = (const float*)d_in[17];
    const float* bo  = (const float*)d_in[18];
    const float* W1  = (const float*)d_in[19];
    const float* b1  = (const float*)d_in[20];
    const float* W2  = (const float*)d_in[21];
    const float* b2  = (const float*)d_in[22];
    const float* g2  = (const float*)d_in[23];
    const float* be2 = (const float*)d_in[24];
    const float* g3  = (const float*)d_in[25];
    const float* be3 = (const float*)d_in[26];
    float* out = (float*)d_out;

    __nv_bfloat16 *Wv_bf, *Wo_bf, *W1_bf, *W2_bf, *Wp2_bf, *Wp3_bf, *Wab_hi, *Wab_lo;
    int8_t* v_i8;
    float *q, *buf1, *buf2, *smp, *xq, *bab;
    cudaGetSymbolAddress((void**)&v_i8,   g_v_i8);
    cudaGetSymbolAddress((void**)&q,      g_q);
    cudaGetSymbolAddress((void**)&buf1,   g_buf1);
    cudaGetSymbolAddress((void**)&buf2,   g_buf2);
    cudaGetSymbolAddress((void**)&smp,    g_smp);
    cudaGetSymbolAddress((void**)&xq,     g_xq);
    cudaGetSymbolAddress((void**)&Wv_bf,  g_Wv_bf);
    cudaGetSymbolAddress((void**)&Wo_bf,  g_Wo_bf);
    cudaGetSymbolAddress((void**)&W1_bf,  g_W1_bf);
    cudaGetSymbolAddress((void**)&W2_bf,  g_W2_bf);
    cudaGetSymbolAddress((void**)&Wp2_bf, g_Wp2_bf);
    cudaGetSymbolAddress((void**)&Wp3_bf, g_Wp3_bf);
    cudaGetSymbolAddress((void**)&Wab_hi, g_Wab_hi);
    cudaGetSymbolAddress((void**)&Wab_lo, g_Wab_lo);
    cudaGetSymbolAddress((void**)&bab,    g_bab);

    cudaFuncSetAttribute(mma_k256_vproj, cudaFuncAttributeMaxDynamicSharedMemorySize, KSMEM_TOTAL);

    static cudaStream_t s1 = nullptr;
    static cudaEvent_t ev_fork = nullptr, ev_join = nullptr, ev_sa = nullptr, ev_done = nullptr;
    if (s1 == nullptr) {
        cudaStreamCreateWithFlags(&s1, cudaStreamNonBlocking);
        cudaEventCreateWithFlags(&ev_fork, cudaEventDisableTiming);
        cudaEventCreateWithFlags(&ev_join, cudaEventDisableTiming);
        cudaEventCreateWithFlags(&ev_sa,   cudaEventDisableTiming);
        cudaEventCreateWithFlags(&ev_done, cudaEventDisableTiming);
    }

    // (1) Wv conversion — sole gate for vproj
    prep_wv<<<(DIM * DIM + 255) / 256, 256>>>(Wv, Wv_bf);

    // Fork: (2) vproj on side stream
    cudaEventRecord(ev_fork, 0);
    cudaStreamWaitEvent(s1, ev_fork, 0);
    mma_k256_vproj<<<HWSZ / 64, 256, KSMEM_TOTAL, s1>>>(memory, Wv_bf, bv, v_i8);
    cudaEventRecord(ev_join, s1);

    // Main branch (overlaps vproj)
    prep_rest<<<((3 * DIM * DIM + 2 * DFF * DIM) + 255) / 256, 256>>>(
        Wo, Wo_bf, Wp2, Wp2_bf, Wp3, Wp3_bf, W1, W1_bf, W2, W2_bf);
    pack_wab<<<DIM, DIM>>>(Wa, Wb, ba, bb, Wab_hi, Wab_lo, bab);
    sgemm_k8_relu<<<dim3(DIM / BN, NQ / BM), 256>>>(ref_w, Wp1, bp1, buf1, NQ, DIM, 8);
    mma_gemm64<1><<<dim3(2, NQ / 64), 256>>>(buf1, Wp2_bf, bp2, nullptr, buf2, DIM, DIM);
    mma_gemm64<2><<<dim3(2, NQ / 64), 256>>>(buf2, Wp3_bf, bp3, query, q, DIM, DIM);
    mma_gemm64_x3<<<dim3(2, NQ / 64), 256>>>(q, Wab_hi, Wab_lo, bab, buf1, DIM, DIM);

    TailArgs t{query, g2, be2, g3, be3, bo, b1, b2,
               Wo_bf, W1_bf, W2_bf, smp, buf1, buf2, xq, out};

    // Join + pipelined halves
    cudaStreamWaitEvent(0, ev_join, 0);
    sample_kernel<<<NHALF, 256>>>(ref_w, buf1, v_i8, smp);
    cudaEventRecord(ev_sa, 0);
    cudaStreamWaitEvent(s1, ev_sa, 0);
    sample_kernel<<<NHALF, 256, 0, s1>>>(
        ref_w + (size_t)NHALF * 8, buf1 + (size_t)NHALF * DIM, v_i8,
        smp + (size_t)NHALF * DIM);
    launch_tail_half(t, 0, 0);
    launch_tail_half(t, NHALF, s1);

    cudaEventRecord(ev_done, s1);
    cudaStreamWaitEvent(0, ev_done, 0);
}